// round 1
// baseline (speedup 1.0000x reference)
#include <cuda_runtime.h>
#include <math.h>

// Problem constants
#define Bn 4
#define Sn 2048
#define Dn 1024
#define Hn 16
#define HDn 64
#define N3 3072   // 3*Dn

// ---------------------------------------------------------------------------
// Device scratch (no cudaMalloc allowed)
// g_q, g_k laid out [B, H, Hd, S]   (transposed: coalesced K-major attention tiles)
// g_v laid out      [B, H, S, Hd]
// g_ctx             [B, S, D]
// g_proj            [B, S, D]
// ---------------------------------------------------------------------------
__device__ float g_q[Bn * Hn * HDn * Sn];
__device__ float g_k[Bn * Hn * HDn * Sn];
__device__ float g_v[Bn * Hn * Sn * HDn];
__device__ float g_ctx[Bn * Sn * Dn];
__device__ float g_proj[Bn * Sn * Dn];

// ---------------------------------------------------------------------------
// Kernel 1: QKV GEMM  (M=8192, N=3072, K=1024), fp32, 128x64 block tile,
// BK=16, 256 threads, 8x4 per-thread micro-tile. Epilogue adds bias and
// scatters into g_q / g_k / g_v with the attention-friendly layouts.
// Grid: (3072/64, 8192/128) = (48, 64)
// ---------------------------------------------------------------------------
__global__ __launch_bounds__(256) void qkv_gemm_kernel(
    const float* __restrict__ x, const float* __restrict__ W,
    const float* __restrict__ bias) {
  __shared__ __align__(16) float As[16][132];  // [k][m], padded vs bank conflicts
  __shared__ __align__(16) float Bs[16][68];   // [k][n]

  const int t  = threadIdx.x;
  const int tx = t & 15;      // 0..15 -> 4 output cols
  const int ty = t >> 4;      // 0..15 -> 8 output rows
  const int n0 = blockIdx.x * 64;
  const int m0 = blockIdx.y * 128;

  float acc[8][4];
#pragma unroll
  for (int a = 0; a < 8; a++)
#pragma unroll
    for (int j = 0; j < 4; j++) acc[a][j] = 0.0f;

  for (int k0 = 0; k0 < Dn; k0 += 16) {
    // Load A tile (128x16) transposed into As[k][m]
#pragma unroll
    for (int i = 0; i < 2; i++) {
      int idx = t + i * 256;            // 0..511 float4s
      int row = idx >> 2;               // 0..127
      int c4  = idx & 3;                // 0..3
      float4 v = *(const float4*)&x[(size_t)(m0 + row) * Dn + k0 + c4 * 4];
      As[c4 * 4 + 0][row] = v.x;
      As[c4 * 4 + 1][row] = v.y;
      As[c4 * 4 + 2][row] = v.z;
      As[c4 * 4 + 3][row] = v.w;
    }
    // Load B tile (16x64)
    {
      int row = t >> 4;                 // 0..15
      int c4  = t & 15;                 // 0..15
      float4 v = *(const float4*)&W[(size_t)(k0 + row) * N3 + n0 + c4 * 4];
      *(float4*)&Bs[row][c4 * 4] = v;
    }
    __syncthreads();

#pragma unroll
    for (int k = 0; k < 16; k++) {
      float4 a0 = *(float4*)&As[k][ty * 8];
      float4 a1 = *(float4*)&As[k][ty * 8 + 4];
      float4 b0 = *(float4*)&Bs[k][tx * 4];
      float ar[8] = {a0.x, a0.y, a0.z, a0.w, a1.x, a1.y, a1.z, a1.w};
      float br[4] = {b0.x, b0.y, b0.z, b0.w};
#pragma unroll
      for (int a = 0; a < 8; a++)
#pragma unroll
        for (int j = 0; j < 4; j++)
          acc[a][j] = fmaf(ar[a], br[j], acc[a][j]);
    }
    __syncthreads();
  }

  // Epilogue: bias + scatter. Block's 64 cols live in exactly one section and
  // one head (n0 is a multiple of 64).
  const int sec = n0 >> 10;              // 0=Q, 1=K, 2=V
  const int hq  = (n0 & 1023) >> 6;      // head
#pragma unroll
  for (int a = 0; a < 8; a++) {
    const int m  = m0 + ty * 8 + a;
    const int bb = m >> 11;              // batch
    const int s  = m & 2047;             // seq pos
#pragma unroll
    for (int j = 0; j < 4; j++) {
      const int hd = tx * 4 + j;
      const int n  = n0 + hd;
      const float val = acc[a][j] + bias[n];
      if (sec == 0) {
        g_q[((size_t)(bb * Hn + hq) * HDn + hd) * Sn + s] = val;
      } else if (sec == 1) {
        g_k[((size_t)(bb * Hn + hq) * HDn + hd) * Sn + s] = val;
      } else {
        g_v[((size_t)(bb * Hn + hq) * Sn + s) * HDn + hd] = val;
      }
    }
  }
}

// ---------------------------------------------------------------------------
// Kernel 2: flash attention, fp32. One block = 64 query rows of one (b,h).
// 256 threads (16x16), 4x4 micro-tiles for both QK^T and PV GEMMs.
// Online softmax with 16-lane shuffle row reductions.
// Shared: Qt[64][64](d,i)  Kt[64][64](d,j)  Vs[64][64](j,n)  Ps[64][64](i,j)
//   = 64 KB dynamic shared memory.
// Grid: (2048/64, 16, 4) = (32, 16, 4)
// ---------------------------------------------------------------------------
__global__ __launch_bounds__(256) void attn_kernel() {
  extern __shared__ float sm[];
  float* Qt = sm;              // [d][i]
  float* Kt = sm + 4096;       // [d][j]
  float* Vs = sm + 8192;       // [j][n]
  float* Ps = sm + 12288;      // [i][j]

  const int t  = threadIdx.x;
  const int tx = t & 15;
  const int ty = t >> 4;
  const int b  = blockIdx.z;
  const int h  = blockIdx.y;
  const int s0 = blockIdx.x * 64;

  const size_t baseQK = (size_t)(b * Hn + h) * HDn * Sn;
  const size_t baseV  = (size_t)(b * Hn + h) * Sn * HDn;

  // Load Q tile, pre-scaled by 1/sqrt(Hd)
  const float scale = 0.125f;
#pragma unroll
  for (int i = 0; i < 4; i++) {
    int idx = t + i * 256;        // 0..1023 float4s
    int d   = idx >> 4;           // 0..63
    int c   = (idx & 15) * 4;     // 0..60
    float4 v = *(const float4*)&g_q[baseQK + (size_t)d * Sn + s0 + c];
    v.x *= scale; v.y *= scale; v.z *= scale; v.w *= scale;
    *(float4*)&Qt[d * 64 + c] = v;
  }

  float acc[4][4];
  float mrow[4], lrow[4];
#pragma unroll
  for (int a = 0; a < 4; a++) {
    mrow[a] = -INFINITY;
    lrow[a] = 0.0f;
#pragma unroll
    for (int j = 0; j < 4; j++) acc[a][j] = 0.0f;
  }

  for (int k0 = 0; k0 < Sn; k0 += 64) {
    __syncthreads();  // protect Kt/Vs/Ps reuse from previous iteration
#pragma unroll
    for (int i = 0; i < 4; i++) {
      int idx = t + i * 256;
      int d   = idx >> 4;
      int c   = (idx & 15) * 4;
      *(float4*)&Kt[d * 64 + c] =
          *(const float4*)&g_k[baseQK + (size_t)d * Sn + k0 + c];
      *(float4*)&Vs[d * 64 + c] =
          *(const float4*)&g_v[baseV + (size_t)(k0 + d) * HDn + c];
    }
    __syncthreads();

    // S = (Q*scale) K^T : 4x4 per thread
    float s[4][4];
#pragma unroll
    for (int a = 0; a < 4; a++)
#pragma unroll
      for (int j = 0; j < 4; j++) s[a][j] = 0.0f;

#pragma unroll 8
    for (int d = 0; d < 64; d++) {
      float4 qa = *(float4*)&Qt[d * 64 + ty * 4];
      float4 kb = *(float4*)&Kt[d * 64 + tx * 4];
      float ar[4] = {qa.x, qa.y, qa.z, qa.w};
      float br[4] = {kb.x, kb.y, kb.z, kb.w};
#pragma unroll
      for (int a = 0; a < 4; a++)
#pragma unroll
        for (int j = 0; j < 4; j++)
          s[a][j] = fmaf(ar[a], br[j], s[a][j]);
    }

    // Online softmax update per owned row (row reduction across 16 tx lanes)
#pragma unroll
    for (int a = 0; a < 4; a++) {
      float rm = fmaxf(fmaxf(s[a][0], s[a][1]), fmaxf(s[a][2], s[a][3]));
#pragma unroll
      for (int o = 8; o; o >>= 1)
        rm = fmaxf(rm, __shfl_xor_sync(0xffffffffu, rm, o));
      float mnew = fmaxf(mrow[a], rm);
      float corr = __expf(mrow[a] - mnew);
      mrow[a] = mnew;
      float4 p;
      p.x = __expf(s[a][0] - mnew);
      p.y = __expf(s[a][1] - mnew);
      p.z = __expf(s[a][2] - mnew);
      p.w = __expf(s[a][3] - mnew);
      float rs = p.x + p.y + p.z + p.w;
#pragma unroll
      for (int o = 8; o; o >>= 1) rs += __shfl_xor_sync(0xffffffffu, rs, o);
      lrow[a] = lrow[a] * corr + rs;
#pragma unroll
      for (int j = 0; j < 4; j++) acc[a][j] *= corr;
      *(float4*)&Ps[(ty * 4 + a) * 64 + tx * 4] = p;
    }
    __syncthreads();

    // acc += P @ V
#pragma unroll 8
    for (int j = 0; j < 64; j++) {
      float4 v = *(float4*)&Vs[j * 64 + tx * 4];
      float br[4] = {v.x, v.y, v.z, v.w};
#pragma unroll
      for (int a = 0; a < 4; a++) {
        float p = Ps[(ty * 4 + a) * 64 + j];
#pragma unroll
        for (int c = 0; c < 4; c++)
          acc[a][c] = fmaf(p, br[c], acc[a][c]);
      }
    }
  }

  // Normalize and write context [B,S,D]
#pragma unroll
  for (int a = 0; a < 4; a++) {
    const float inv = 1.0f / lrow[a];
    const int srow = s0 + ty * 4 + a;
    float4 o;
    o.x = acc[a][0] * inv;
    o.y = acc[a][1] * inv;
    o.z = acc[a][2] * inv;
    o.w = acc[a][3] * inv;
    *(float4*)&g_ctx[((size_t)(b * Sn + srow)) * Dn + h * HDn + tx * 4] = o;
  }
}

// ---------------------------------------------------------------------------
// Kernel 3: output projection GEMM (M=8192, N=1024, K=1024) + bias -> g_proj
// Same tiling as kernel 1. Grid: (1024/64, 8192/128) = (16, 64)
// ---------------------------------------------------------------------------
__global__ __launch_bounds__(256) void out_gemm_kernel(
    const float* __restrict__ W, const float* __restrict__ bias) {
  __shared__ __align__(16) float As[16][132];
  __shared__ __align__(16) float Bs[16][68];

  const int t  = threadIdx.x;
  const int tx = t & 15;
  const int ty = t >> 4;
  const int n0 = blockIdx.x * 64;
  const int m0 = blockIdx.y * 128;

  float acc[8][4];
#pragma unroll
  for (int a = 0; a < 8; a++)
#pragma unroll
    for (int j = 0; j < 4; j++) acc[a][j] = 0.0f;

  for (int k0 = 0; k0 < Dn; k0 += 16) {
#pragma unroll
    for (int i = 0; i < 2; i++) {
      int idx = t + i * 256;
      int row = idx >> 2;
      int c4  = idx & 3;
      float4 v = *(const float4*)&g_ctx[(size_t)(m0 + row) * Dn + k0 + c4 * 4];
      As[c4 * 4 + 0][row] = v.x;
      As[c4 * 4 + 1][row] = v.y;
      As[c4 * 4 + 2][row] = v.z;
      As[c4 * 4 + 3][row] = v.w;
    }
    {
      int row = t >> 4;
      int c4  = t & 15;
      float4 v = *(const float4*)&W[(size_t)(k0 + row) * Dn + n0 + c4 * 4];
      *(float4*)&Bs[row][c4 * 4] = v;
    }
    __syncthreads();

#pragma unroll
    for (int k = 0; k < 16; k++) {
      float4 a0 = *(float4*)&As[k][ty * 8];
      float4 a1 = *(float4*)&As[k][ty * 8 + 4];
      float4 b0 = *(float4*)&Bs[k][tx * 4];
      float ar[8] = {a0.x, a0.y, a0.z, a0.w, a1.x, a1.y, a1.z, a1.w};
      float br[4] = {b0.x, b0.y, b0.z, b0.w};
#pragma unroll
      for (int a = 0; a < 8; a++)
#pragma unroll
        for (int j = 0; j < 4; j++)
          acc[a][j] = fmaf(ar[a], br[j], acc[a][j]);
    }
    __syncthreads();
  }

#pragma unroll
  for (int a = 0; a < 8; a++) {
    const int m = m0 + ty * 8 + a;
#pragma unroll
    for (int j = 0; j < 4; j++) {
      const int n = n0 + tx * 4 + j;
      g_proj[(size_t)m * Dn + n] = acc[a][j] + bias[n];
    }
  }
}

// ---------------------------------------------------------------------------
// Kernel 4: residual add + LayerNorm. One block per row (1024 cols, 256 thr,
// 4 elems/thread). Grid: 8192
// ---------------------------------------------------------------------------
__device__ __forceinline__ float block_sum(float v, float* red) {
#pragma unroll
  for (int o = 16; o; o >>= 1) v += __shfl_xor_sync(0xffffffffu, v, o);
  if ((threadIdx.x & 31) == 0) red[threadIdx.x >> 5] = v;
  __syncthreads();
  float tot = red[0] + red[1] + red[2] + red[3] +
              red[4] + red[5] + red[6] + red[7];
  __syncthreads();
  return tot;
}

__global__ __launch_bounds__(256) void ln_kernel(
    const float* __restrict__ x, const float* __restrict__ gamma,
    const float* __restrict__ beta, float* __restrict__ out) {
  __shared__ float red[8];
  const int row = blockIdx.x;
  const int c   = threadIdx.x * 4;

  float4 y  = *(const float4*)&g_proj[(size_t)row * Dn + c];
  float4 xv = *(const float4*)&x[(size_t)row * Dn + c];
  y.x += xv.x; y.y += xv.y; y.z += xv.z; y.w += xv.w;

  float tot = block_sum(y.x + y.y + y.z + y.w, red);
  const float mu = tot * (1.0f / Dn);

  float dx = y.x - mu, dy = y.y - mu, dz = y.z - mu, dw = y.w - mu;
  float sq = block_sum(dx * dx + dy * dy + dz * dz + dw * dw, red);
  const float var = sq * (1.0f / Dn);
  const float r = rsqrtf(var + 1e-5f);

  float4 g = *(const float4*)&gamma[c];
  float4 bt = *(const float4*)&beta[c];
  float4 o;
  o.x = dx * r * g.x + bt.x;
  o.y = dy * r * g.y + bt.y;
  o.z = dz * r * g.z + bt.z;
  o.w = dw * r * g.w + bt.w;
  *(float4*)&out[(size_t)row * Dn + c] = o;
}

// ---------------------------------------------------------------------------
// Launch
// ---------------------------------------------------------------------------
extern "C" void kernel_launch(void* const* d_in, const int* in_sizes, int n_in,
                              void* d_out, int out_size) {
  (void)in_sizes; (void)n_in; (void)out_size;
  const float* x     = (const float*)d_in[0];
  const float* W_qkv = (const float*)d_in[1];
  const float* b_qkv = (const float*)d_in[2];
  const float* W_out = (const float*)d_in[3];
  const float* b_out = (const float*)d_in[4];
  const float* gamma = (const float*)d_in[5];
  const float* beta  = (const float*)d_in[6];
  float* out = (float*)d_out;

  cudaFuncSetAttribute(attn_kernel, cudaFuncAttributeMaxDynamicSharedMemorySize,
                       65536);

  qkv_gemm_kernel<<<dim3(N3 / 64, (Bn * Sn) / 128), 256>>>(x, W_qkv, b_qkv);
  attn_kernel<<<dim3(Sn / 64, Hn, Bn), 256, 65536>>>();
  out_gemm_kernel<<<dim3(Dn / 64, (Bn * Sn) / 128), 256>>>(W_out, b_out);
  ln_kernel<<<Bn * Sn, 256>>>(x, gamma, beta, out);
}

// round 5
// speedup vs baseline: 2.4494x; 2.4494x over previous
#include <cuda_runtime.h>
#include <math.h>

// Problem constants
#define Bn 4
#define Sn 2048
#define Dn 1024
#define Hn 16
#define HDn 64
#define N3 3072   // 3*Dn

// ---------------------------------------------------------------------------
// Device scratch
// g_q : [B, H, S, Hd]   (mma A operand: rows=query, cols=d)
// g_k : [B, H, Hd, S]   (mma B operand for QK^T: rows=d, cols=key)
// g_v : [B, H, S, Hd]   (mma B operand for PV:  rows=key, cols=d)
// NOTE: these symbols are referenced ONLY inside device code. Passing a
// __device__ array from host code (as R2-R4 did with g_ctx) passes the host
// shadow object's address -> GPU reads host BSS via ATS on the Grace host and
// the driver moves 128 MiB of device memory, tripping the alloc guard.
// ---------------------------------------------------------------------------
__device__ float g_q[(size_t)Bn * Hn * Sn * HDn];
__device__ float g_k[(size_t)Bn * Hn * HDn * Sn];
__device__ float g_v[(size_t)Bn * Hn * Sn * HDn];
__device__ float g_ctx[(size_t)Bn * Sn * Dn];
__device__ float g_proj[(size_t)Bn * Sn * Dn];

// ---------------------------------------------------------------------------
// TF32 helpers
// ---------------------------------------------------------------------------
__device__ __forceinline__ unsigned f2t(float f) {
  unsigned u;
  asm("cvt.rna.tf32.f32 %0, %1;" : "=r"(u) : "f"(f));
  return u;
}
__device__ __forceinline__ float f2tf(float f) { return __uint_as_float(f2t(f)); }

#define MMA_TF32(c0, c1, c2, c3, a0, a1, a2, a3, b0, b1)                     \
  asm volatile(                                                              \
      "mma.sync.aligned.m16n8k8.row.col.f32.tf32.tf32.f32 "                  \
      "{%0,%1,%2,%3},{%4,%5,%6,%7},{%8,%9},{%0,%1,%2,%3};"                   \
      : "+f"(c0), "+f"(c1), "+f"(c2), "+f"(c3)                               \
      : "r"(a0), "r"(a1), "r"(a2), "r"(a3), "r"(b0), "r"(b1))

// ---------------------------------------------------------------------------
// QKV scatter epilogue helper
// ---------------------------------------------------------------------------
__device__ __forceinline__ void scatter_qkv(int m, int n, float val) {
  const int sec = n >> 10;            // 0=Q,1=K,2=V
  const int h   = (n & 1023) >> 6;
  const int hd  = n & 63;
  const int b   = m >> 11;
  const int s   = m & 2047;
  if (sec == 0)
    g_q[((size_t)(b * Hn + h) * Sn + s) * HDn + hd] = val;
  else if (sec == 1)
    g_k[((size_t)(b * Hn + h) * HDn + hd) * Sn + s] = val;
  else
    g_v[((size_t)(b * Hn + h) * Sn + s) * HDn + hd] = val;
}

// ---------------------------------------------------------------------------
// TF32 GEMM: C[M=8192, N=NDIM] = Asrc[8192,1024] @ W[1024,NDIM] + bias
// Block 128x128, BK=32, 256 threads, 8 warps (4x2), warp tile 32x64.
// MODE 0: Asrc = g_ctx (device symbol, resolved IN KERNEL), write g_proj.
// MODE 1: Asrc = A param (harness input x), QKV scatter.
// ---------------------------------------------------------------------------
#define GEMM_LOAD_A(dst, i, kk)                                              \
  {                                                                          \
    int idx = t + (i) * 256;                                                 \
    int row = idx >> 3, c4 = idx & 7;                                        \
    dst = *(const float4*)&Asrc[(size_t)(m0 + row) * Dn + (kk) + c4 * 4];    \
  }
#define GEMM_LOAD_B(dst, i, kk)                                              \
  {                                                                          \
    int idx = t + (i) * 256;                                                 \
    int row = idx >> 5, c4 = idx & 31;                                       \
    dst = *(const float4*)&W[(size_t)((kk) + row) * NDIM + n0 + c4 * 4];     \
  }
#define GEMM_STORE_A(src, i)                                                 \
  {                                                                          \
    int idx = t + (i) * 256;                                                 \
    int row = idx >> 3, c = (idx & 7) * 4;                                   \
    As[row][c + 0] = f2tf(src.x);                                            \
    As[row][c + 1] = f2tf(src.y);                                            \
    As[row][c + 2] = f2tf(src.z);                                            \
    As[row][c + 3] = f2tf(src.w);                                            \
  }
#define GEMM_STORE_B(src, i)                                                 \
  {                                                                          \
    int idx = t + (i) * 256;                                                 \
    int row = idx >> 5, c = (idx & 31) * 4;                                  \
    Bs[row][c + 0] = f2tf(src.x);                                            \
    Bs[row][c + 1] = f2tf(src.y);                                            \
    Bs[row][c + 2] = f2tf(src.z);                                            \
    Bs[row][c + 3] = f2tf(src.w);                                            \
  }

template <int NDIM, int MODE>
__global__ __launch_bounds__(256) void gemm_tf32_kernel(
    const float* __restrict__ A, const float* __restrict__ W,
    const float* __restrict__ bias) {
  __shared__ __align__(16) float As[128][36];   // [m][k], tf32 bits
  __shared__ __align__(16) float Bs[32][132];   // [k][n], tf32 bits

  // Resolve input source in DEVICE code: g_ctx decays to a real device ptr.
  const float* __restrict__ Asrc = (MODE == 0) ? (const float*)g_ctx : A;

  const int t    = threadIdx.x;
  const int lane = t & 31;
  const int warp = t >> 5;
  const int wm   = warp >> 1;   // 0..3
  const int wn   = warp & 1;    // 0..1
  const int n0   = blockIdx.x * 128;
  const int m0   = blockIdx.y * 128;

  float4 ra0, ra1, ra2, ra3, rb0, rb1, rb2, rb3;

  float acc[2][8][4];
#pragma unroll
  for (int mt = 0; mt < 2; mt++)
#pragma unroll
    for (int nt = 0; nt < 8; nt++)
#pragma unroll
      for (int j = 0; j < 4; j++) acc[mt][nt][j] = 0.0f;

  GEMM_LOAD_A(ra0, 0, 0) GEMM_LOAD_A(ra1, 1, 0)
  GEMM_LOAD_A(ra2, 2, 0) GEMM_LOAD_A(ra3, 3, 0)
  GEMM_LOAD_B(rb0, 0, 0) GEMM_LOAD_B(rb1, 1, 0)
  GEMM_LOAD_B(rb2, 2, 0) GEMM_LOAD_B(rb3, 3, 0)
  GEMM_STORE_A(ra0, 0) GEMM_STORE_A(ra1, 1)
  GEMM_STORE_A(ra2, 2) GEMM_STORE_A(ra3, 3)
  GEMM_STORE_B(rb0, 0) GEMM_STORE_B(rb1, 1)
  GEMM_STORE_B(rb2, 2) GEMM_STORE_B(rb3, 3)
  __syncthreads();

  for (int it = 0; it < Dn / 32; it++) {
    if (it + 1 < Dn / 32) {
      const int kn = (it + 1) * 32;
      GEMM_LOAD_A(ra0, 0, kn) GEMM_LOAD_A(ra1, 1, kn)
      GEMM_LOAD_A(ra2, 2, kn) GEMM_LOAD_A(ra3, 3, kn)
      GEMM_LOAD_B(rb0, 0, kn) GEMM_LOAD_B(rb1, 1, kn)
      GEMM_LOAD_B(rb2, 2, kn) GEMM_LOAD_B(rb3, 3, kn)
    }

#pragma unroll
    for (int ks = 0; ks < 4; ks++) {
      const int kb = ks * 8;
      unsigned a00, a01, a02, a03, a10, a11, a12, a13;
      {
        int r = wm * 32 + (lane >> 2);
        int c = kb + (lane & 3);
        a00 = __float_as_uint(As[r][c]);
        a01 = __float_as_uint(As[r + 8][c]);
        a02 = __float_as_uint(As[r][c + 4]);
        a03 = __float_as_uint(As[r + 8][c + 4]);
        a10 = __float_as_uint(As[r + 16][c]);
        a11 = __float_as_uint(As[r + 24][c]);
        a12 = __float_as_uint(As[r + 16][c + 4]);
        a13 = __float_as_uint(As[r + 24][c + 4]);
      }
#pragma unroll
      for (int nt = 0; nt < 8; nt++) {
        int n  = wn * 64 + nt * 8 + (lane >> 2);
        int kk = kb + (lane & 3);
        unsigned b0 = __float_as_uint(Bs[kk][n]);
        unsigned b1 = __float_as_uint(Bs[kk + 4][n]);
        MMA_TF32(acc[0][nt][0], acc[0][nt][1], acc[0][nt][2], acc[0][nt][3],
                 a00, a01, a02, a03, b0, b1);
        MMA_TF32(acc[1][nt][0], acc[1][nt][1], acc[1][nt][2], acc[1][nt][3],
                 a10, a11, a12, a13, b0, b1);
      }
    }
    __syncthreads();
    if (it + 1 < Dn / 32) {
      GEMM_STORE_A(ra0, 0) GEMM_STORE_A(ra1, 1)
      GEMM_STORE_A(ra2, 2) GEMM_STORE_A(ra3, 3)
      GEMM_STORE_B(rb0, 0) GEMM_STORE_B(rb1, 1)
      GEMM_STORE_B(rb2, 2) GEMM_STORE_B(rb3, 3)
      __syncthreads();
    }
  }

  // Epilogue
#pragma unroll
  for (int mt = 0; mt < 2; mt++) {
    const int r0 = m0 + wm * 32 + mt * 16 + (lane >> 2);
#pragma unroll
    for (int nt = 0; nt < 8; nt++) {
      const int c0 = n0 + wn * 64 + nt * 8 + (lane & 3) * 2;
      float v0 = acc[mt][nt][0] + bias[c0];
      float v1 = acc[mt][nt][1] + bias[c0 + 1];
      float v2 = acc[mt][nt][2] + bias[c0];
      float v3 = acc[mt][nt][3] + bias[c0 + 1];
      if (MODE == 0) {
        g_proj[(size_t)r0 * Dn + c0]           = v0;
        g_proj[(size_t)r0 * Dn + c0 + 1]       = v1;
        g_proj[(size_t)(r0 + 8) * Dn + c0]     = v2;
        g_proj[(size_t)(r0 + 8) * Dn + c0 + 1] = v3;
      } else {
        scatter_qkv(r0, c0, v0);
        scatter_qkv(r0, c0 + 1, v1);
        scatter_qkv(r0 + 8, c0, v2);
        scatter_qkv(r0 + 8, c0 + 1, v3);
      }
    }
  }
}

// ---------------------------------------------------------------------------
// Flash attention, TF32 mma. Block = 128 queries of one (b,h).
// 256 threads, 8 warps (4x2), warp tile 32x32 for both S=QK^T and O+=PV.
// Key tiles of 64. Online softmax in fp32 via shared.
// Shared: Qs[128][68] Ps[128][68] Ks[64][68] Vs[64][68] crow[128]
// Grid: (16, 16, 4)
// ---------------------------------------------------------------------------
__global__ __launch_bounds__(256) void attn_tf32_kernel() {
  extern __shared__ float sm[];
  float* Qs   = sm;                    // [q][d]  tf32 bits, prescaled
  float* Ps   = Qs + 128 * 68;         // [q][key] fp32 scores -> tf32 P
  float* Ks   = Ps + 128 * 68;         // [d][key] tf32 bits
  float* Vs   = Ks + 64 * 68;          // [key][d] tf32 bits
  float* crow = Vs + 64 * 68;          // [128]

  const int t    = threadIdx.x;
  const int lane = t & 31;
  const int warp = t >> 5;
  const int wm   = warp >> 1;  // 0..3
  const int wn   = warp & 1;   // 0..1
  const int b    = blockIdx.z;
  const int h    = blockIdx.y;
  const int s0   = blockIdx.x * 128;

  const size_t baseQ = (size_t)(b * Hn + h) * Sn * HDn;
  const size_t baseK = (size_t)(b * Hn + h) * HDn * Sn;
  const size_t baseV = (size_t)(b * Hn + h) * Sn * HDn;

  // Load Q tile once: scale by 1/sqrt(64)=0.125, convert to tf32
#pragma unroll
  for (int i = 0; i < 8; i++) {
    int idx = t + i * 256;
    int row = idx >> 4, c = (idx & 15) * 4;
    float4 v = *(const float4*)&g_q[baseQ + (size_t)(s0 + row) * HDn + c];
    Qs[row * 68 + c + 0] = f2tf(v.x * 0.125f);
    Qs[row * 68 + c + 1] = f2tf(v.y * 0.125f);
    Qs[row * 68 + c + 2] = f2tf(v.z * 0.125f);
    Qs[row * 68 + c + 3] = f2tf(v.w * 0.125f);
  }

  // Softmax-role state: this thread owns row (t>>1), half (t&1)
  float m_run = -INFINITY, l_run = 0.0f;

  float acc_o[2][4][4];
#pragma unroll
  for (int mt = 0; mt < 2; mt++)
#pragma unroll
    for (int nt = 0; nt < 4; nt++)
#pragma unroll
      for (int j = 0; j < 4; j++) acc_o[mt][nt][j] = 0.0f;

  for (int k0 = 0; k0 < Sn; k0 += 64) {
    __syncthreads();  // protect Ks/Vs (prev PV) and Ps (prev PV reads)
    // Load K tile [d][key] and V tile [key][d]
#pragma unroll
    for (int i = 0; i < 4; i++) {
      int idx = t + i * 256;
      int row = idx >> 4, c = (idx & 15) * 4;
      float4 kv = *(const float4*)&g_k[baseK + (size_t)row * Sn + k0 + c];
      Ks[row * 68 + c + 0] = f2tf(kv.x);
      Ks[row * 68 + c + 1] = f2tf(kv.y);
      Ks[row * 68 + c + 2] = f2tf(kv.z);
      Ks[row * 68 + c + 3] = f2tf(kv.w);
      float4 vv = *(const float4*)&g_v[baseV + (size_t)(k0 + row) * HDn + c];
      Vs[row * 68 + c + 0] = f2tf(vv.x);
      Vs[row * 68 + c + 1] = f2tf(vv.y);
      Vs[row * 68 + c + 2] = f2tf(vv.z);
      Vs[row * 68 + c + 3] = f2tf(vv.w);
    }
    __syncthreads();

    // S = Q K^T   (warp tile 32x32)
    float accs[2][4][4];
#pragma unroll
    for (int mt = 0; mt < 2; mt++)
#pragma unroll
      for (int nt = 0; nt < 4; nt++)
#pragma unroll
        for (int j = 0; j < 4; j++) accs[mt][nt][j] = 0.0f;

#pragma unroll
    for (int ks = 0; ks < 8; ks++) {
      const int kb = ks * 8;
      unsigned a00, a01, a02, a03, a10, a11, a12, a13;
      {
        int r = wm * 32 + (lane >> 2);
        int c = kb + (lane & 3);
        a00 = __float_as_uint(Qs[r * 68 + c]);
        a01 = __float_as_uint(Qs[(r + 8) * 68 + c]);
        a02 = __float_as_uint(Qs[r * 68 + c + 4]);
        a03 = __float_as_uint(Qs[(r + 8) * 68 + c + 4]);
        a10 = __float_as_uint(Qs[(r + 16) * 68 + c]);
        a11 = __float_as_uint(Qs[(r + 24) * 68 + c]);
        a12 = __float_as_uint(Qs[(r + 16) * 68 + c + 4]);
        a13 = __float_as_uint(Qs[(r + 24) * 68 + c + 4]);
      }
#pragma unroll
      for (int nt = 0; nt < 4; nt++) {
        int n  = wn * 32 + nt * 8 + (lane >> 2);
        int kk = kb + (lane & 3);
        unsigned b0 = __float_as_uint(Ks[kk * 68 + n]);
        unsigned b1 = __float_as_uint(Ks[(kk + 4) * 68 + n]);
        MMA_TF32(accs[0][nt][0], accs[0][nt][1], accs[0][nt][2], accs[0][nt][3],
                 a00, a01, a02, a03, b0, b1);
        MMA_TF32(accs[1][nt][0], accs[1][nt][1], accs[1][nt][2], accs[1][nt][3],
                 a10, a11, a12, a13, b0, b1);
      }
    }

    // Write raw fp32 scores to Ps
#pragma unroll
    for (int mt = 0; mt < 2; mt++) {
      int r = wm * 32 + mt * 16 + (lane >> 2);
#pragma unroll
      for (int nt = 0; nt < 4; nt++) {
        int c = wn * 32 + nt * 8 + (lane & 3) * 2;
        Ps[r * 68 + c]           = accs[mt][nt][0];
        Ps[r * 68 + c + 1]       = accs[mt][nt][1];
        Ps[(r + 8) * 68 + c]     = accs[mt][nt][2];
        Ps[(r + 8) * 68 + c + 1] = accs[mt][nt][3];
      }
    }
    __syncthreads();

    // Online softmax: row = t>>1, half = t&1 owns 32 cols
    {
      const int row = t >> 1;
      const int cb  = (t & 1) * 32;
      float mx = -INFINITY;
#pragma unroll
      for (int j = 0; j < 32; j += 4) {
        float4 v4 = *(float4*)&Ps[row * 68 + cb + j];
        mx = fmaxf(mx, fmaxf(fmaxf(v4.x, v4.y), fmaxf(v4.z, v4.w)));
      }
      mx = fmaxf(mx, __shfl_xor_sync(0xffffffffu, mx, 1));
      const float mnew = fmaxf(m_run, mx);
      const float corr = __expf(m_run - mnew);
      float s = 0.0f;
#pragma unroll
      for (int j = 0; j < 32; j += 4) {
        float4 v4 = *(float4*)&Ps[row * 68 + cb + j];
        float p0 = __expf(v4.x - mnew);
        float p1 = __expf(v4.y - mnew);
        float p2 = __expf(v4.z - mnew);
        float p3 = __expf(v4.w - mnew);
        s += (p0 + p1) + (p2 + p3);
        float4 o;
        o.x = f2tf(p0); o.y = f2tf(p1); o.z = f2tf(p2); o.w = f2tf(p3);
        *(float4*)&Ps[row * 68 + cb + j] = o;
      }
      s += __shfl_xor_sync(0xffffffffu, s, 1);
      l_run = l_run * corr + s;
      m_run = mnew;
      if (!(t & 1)) crow[row] = corr;
    }
    __syncthreads();

    // Scale accumulators by correction, then O += P @ V
#pragma unroll
    for (int mt = 0; mt < 2; mt++) {
      int r = wm * 32 + mt * 16 + (lane >> 2);
      float c0 = crow[r], c8 = crow[r + 8];
#pragma unroll
      for (int nt = 0; nt < 4; nt++) {
        acc_o[mt][nt][0] *= c0;
        acc_o[mt][nt][1] *= c0;
        acc_o[mt][nt][2] *= c8;
        acc_o[mt][nt][3] *= c8;
      }
    }

#pragma unroll
    for (int ks = 0; ks < 8; ks++) {
      const int kb = ks * 8;
      unsigned a00, a01, a02, a03, a10, a11, a12, a13;
      {
        int r = wm * 32 + (lane >> 2);
        int c = kb + (lane & 3);
        a00 = __float_as_uint(Ps[r * 68 + c]);
        a01 = __float_as_uint(Ps[(r + 8) * 68 + c]);
        a02 = __float_as_uint(Ps[r * 68 + c + 4]);
        a03 = __float_as_uint(Ps[(r + 8) * 68 + c + 4]);
        a10 = __float_as_uint(Ps[(r + 16) * 68 + c]);
        a11 = __float_as_uint(Ps[(r + 24) * 68 + c]);
        a12 = __float_as_uint(Ps[(r + 16) * 68 + c + 4]);
        a13 = __float_as_uint(Ps[(r + 24) * 68 + c + 4]);
      }
#pragma unroll
      for (int nt = 0; nt < 4; nt++) {
        int n  = wn * 32 + nt * 8 + (lane >> 2);
        int kk = kb + (lane & 3);
        unsigned b0 = __float_as_uint(Vs[kk * 68 + n]);
        unsigned b1 = __float_as_uint(Vs[(kk + 4) * 68 + n]);
        MMA_TF32(acc_o[0][nt][0], acc_o[0][nt][1], acc_o[0][nt][2],
                 acc_o[0][nt][3], a00, a01, a02, a03, b0, b1);
        MMA_TF32(acc_o[1][nt][0], acc_o[1][nt][1], acc_o[1][nt][2],
                 acc_o[1][nt][3], a10, a11, a12, a13, b0, b1);
      }
    }
  }

  // Final normalization: publish 1/l per row, then write context
  if (!(t & 1)) crow[t >> 1] = 1.0f / l_run;
  __syncthreads();

#pragma unroll
  for (int mt = 0; mt < 2; mt++) {
    const int r    = wm * 32 + mt * 16 + (lane >> 2);
    const float i0 = crow[r];
    const float i8 = crow[r + 8];
#pragma unroll
    for (int nt = 0; nt < 4; nt++) {
      const int c = wn * 32 + nt * 8 + (lane & 3) * 2;
      const size_t o0 = (size_t)(b * Sn + s0 + r) * Dn + h * HDn + c;
      const size_t o8 = (size_t)(b * Sn + s0 + r + 8) * Dn + h * HDn + c;
      g_ctx[o0]     = acc_o[mt][nt][0] * i0;
      g_ctx[o0 + 1] = acc_o[mt][nt][1] * i0;
      g_ctx[o8]     = acc_o[mt][nt][2] * i8;
      g_ctx[o8 + 1] = acc_o[mt][nt][3] * i8;
    }
  }
}

// ---------------------------------------------------------------------------
// Residual + LayerNorm
// ---------------------------------------------------------------------------
__device__ __forceinline__ float block_sum(float v, float* red) {
#pragma unroll
  for (int o = 16; o; o >>= 1) v += __shfl_xor_sync(0xffffffffu, v, o);
  if ((threadIdx.x & 31) == 0) red[threadIdx.x >> 5] = v;
  __syncthreads();
  float tot = red[0] + red[1] + red[2] + red[3] +
              red[4] + red[5] + red[6] + red[7];
  __syncthreads();
  return tot;
}

__global__ __launch_bounds__(256) void ln_kernel(
    const float* __restrict__ x, const float* __restrict__ gamma,
    const float* __restrict__ beta, float* __restrict__ out) {
  __shared__ float red[8];
  const int row = blockIdx.x;
  const int c   = threadIdx.x * 4;

  float4 y  = *(const float4*)&g_proj[(size_t)row * Dn + c];
  float4 xv = *(const float4*)&x[(size_t)row * Dn + c];
  y.x += xv.x; y.y += xv.y; y.z += xv.z; y.w += xv.w;

  float tot = block_sum(y.x + y.y + y.z + y.w, red);
  const float mu = tot * (1.0f / Dn);

  float dx = y.x - mu, dy = y.y - mu, dz = y.z - mu, dw = y.w - mu;
  float sq = block_sum(dx * dx + dy * dy + dz * dz + dw * dw, red);
  const float var = sq * (1.0f / Dn);
  const float r = rsqrtf(var + 1e-5f);

  float4 g  = *(const float4*)&gamma[c];
  float4 bt = *(const float4*)&beta[c];
  float4 o;
  o.x = dx * r * g.x + bt.x;
  o.y = dy * r * g.y + bt.y;
  o.z = dz * r * g.z + bt.z;
  o.w = dw * r * g.w + bt.w;
  *(float4*)&out[(size_t)row * Dn + c] = o;
}

// ---------------------------------------------------------------------------
// Launch — only harness-provided pointers cross the host/device boundary.
// ---------------------------------------------------------------------------
extern "C" void kernel_launch(void* const* d_in, const int* in_sizes, int n_in,
                              void* d_out, int out_size) {
  (void)in_sizes; (void)n_in; (void)out_size;
  const float* x     = (const float*)d_in[0];
  const float* W_qkv = (const float*)d_in[1];
  const float* b_qkv = (const float*)d_in[2];
  const float* W_out = (const float*)d_in[3];
  const float* b_out = (const float*)d_in[4];
  const float* gamma = (const float*)d_in[5];
  const float* beta  = (const float*)d_in[6];
  float* out = (float*)d_out;

  const int attn_smem = (128 * 68 * 2 + 64 * 68 * 2 + 128) * 4;  // 104960 B
  cudaFuncSetAttribute(attn_tf32_kernel,
                       cudaFuncAttributeMaxDynamicSharedMemorySize, attn_smem);

  gemm_tf32_kernel<N3, 1><<<dim3(N3 / 128, (Bn * Sn) / 128), 256>>>(
      x, W_qkv, b_qkv);
  attn_tf32_kernel<<<dim3(Sn / 128, Hn, Bn), 256, attn_smem>>>();
  // MODE 0 reads g_ctx via the device symbol inside the kernel; the pointer
  // argument is an unused placeholder (x, a valid device pointer).
  gemm_tf32_kernel<Dn, 0><<<dim3(Dn / 128, (Bn * Sn) / 128), 256>>>(
      x, W_out, b_out);
  ln_kernel<<<Bn * Sn, 256>>>(x, gamma, beta, out);
}

// round 6
// speedup vs baseline: 3.9679x; 1.6200x over previous
#include <cuda_runtime.h>
#include <cuda_fp16.h>
#include <math.h>

// Problem constants
#define Bn 4
#define Sn 2048
#define Dn 1024
#define Hn 16
#define HDn 64
#define N3 3072   // 3*Dn

// ---------------------------------------------------------------------------
// Device scratch (referenced ONLY in device code — see R5 ATS lesson)
// g_qh : [B, H, S, Hd] half, PRE-SCALED by 1/8
// g_kh : [B, H, S, Hd] half
// g_vh : [B, H, Hd, S] half (transposed: PV mma B operand [n=d][k=key])
// g_ctxh: [B, S, D] half
// g_proj: [B, S, D] fp32
// ---------------------------------------------------------------------------
__device__ __half g_qh[(size_t)Bn * Hn * Sn * HDn];
__device__ __half g_kh[(size_t)Bn * Hn * Sn * HDn];
__device__ __half g_vh[(size_t)Bn * Hn * HDn * Sn];
__device__ __half g_ctxh[(size_t)Bn * Sn * Dn];
__device__ float  g_proj[(size_t)Bn * Sn * Dn];

// ---------------------------------------------------------------------------
// Helpers
// ---------------------------------------------------------------------------
// Pack two floats -> f16x2 in a .b32 (lo = first elem, hi = second).
#define F22H(u, lo, hi)                                                      \
  asm("cvt.rn.f16x2.f32 %0, %1, %2;" : "=r"(u) : "f"(hi), "f"(lo))

// fp16 mma, fp32 accumulate. Operands bound directly to lvalues (macro: no
// address-taking -> no local-memory demotion).
#define MMA_F16(c0, c1, c2, c3, a0, a1, a2, a3, b0, b1)                      \
  asm volatile(                                                              \
      "mma.sync.aligned.m16n8k16.row.col.f32.f16.f16.f32 "                   \
      "{%0,%1,%2,%3},{%4,%5,%6,%7},{%8,%9},{%0,%1,%2,%3};"                   \
      : "+f"(c0), "+f"(c1), "+f"(c2), "+f"(c3)                               \
      : "r"(a0), "r"(a1), "r"(a2), "r"(a3), "r"(b0), "r"(b1))

// ---------------------------------------------------------------------------
// QKV scatter epilogue helper (half outputs; Q pre-scaled by 0.125)
// ---------------------------------------------------------------------------
__device__ __forceinline__ void scatter_qkv(int m, int n, float val) {
  const int sec = n >> 10;            // 0=Q,1=K,2=V
  const int h   = (n & 1023) >> 6;
  const int hd  = n & 63;
  const int b   = m >> 11;
  const int s   = m & 2047;
  if (sec == 0)
    g_qh[((size_t)(b * Hn + h) * Sn + s) * HDn + hd] =
        __float2half_rn(val * 0.125f);
  else if (sec == 1)
    g_kh[((size_t)(b * Hn + h) * Sn + s) * HDn + hd] = __float2half_rn(val);
  else
    g_vh[((size_t)(b * Hn + h) * HDn + hd) * Sn + s] = __float2half_rn(val);
}

// ---------------------------------------------------------------------------
// FP16 GEMM: C[8192, NDIM] = Asrc[8192,1024] @ W[1024,NDIM] + bias
// Block 128x128, BK=32, 256 threads, 8 warps (4x2), warp tile 32x64.
// Smem holds f16x2 pairs as uint32:
//   As2[m][kpair]  stride 20  (16 pairs + pad)  — conflict-free
//   Bs2[kpair][n]  stride 136 (128 n + pad)     — conflict-free
// MODE 0: Asrc = g_ctxh (half, raw copy), write g_proj fp32.
// MODE 1: Asrc = x (float, convert), QKV scatter.
// ---------------------------------------------------------------------------
template <int NDIM, int MODE>
__global__ __launch_bounds__(256) void gemm_f16_kernel(
    const float* __restrict__ A, const float* __restrict__ W,
    const float* __restrict__ bias) {
  __shared__ __align__(16) unsigned As2[128][20];
  __shared__ __align__(16) unsigned Bs2[16][136];

  const int t    = threadIdx.x;
  const int lane = t & 31;
  const int lq   = lane >> 2;   // 0..7
  const int lt   = lane & 3;    // 0..3
  const int warp = t >> 5;
  const int wm   = warp >> 1;   // 0..3
  const int wn   = warp & 1;    // 0..1
  const int n0   = blockIdx.x * 128;
  const int m0   = blockIdx.y * 128;

  // Staging registers
  float4 ra0, ra1, ra2, ra3;          // MODE 1 A (fp32)
  uint4  ha0, ha1;                    // MODE 0 A (half chunks)
  float4 rb0, rb1, rb2, rb3;          // W rows (2 items x 2 k-rows)

#define G_LOAD_A(kk)                                                         \
  if (MODE == 1) {                                                           \
    { int idx = t;       int row = idx >> 3, c4 = idx & 7;                   \
      ra0 = *(const float4*)&A[(size_t)(m0 + row) * Dn + (kk) + c4 * 4]; }   \
    { int idx = t + 256; int row = idx >> 3, c4 = idx & 7;                   \
      ra1 = *(const float4*)&A[(size_t)(m0 + row) * Dn + (kk) + c4 * 4]; }   \
    { int idx = t + 512; int row = idx >> 3, c4 = idx & 7;                   \
      ra2 = *(const float4*)&A[(size_t)(m0 + row) * Dn + (kk) + c4 * 4]; }   \
    { int idx = t + 768; int row = idx >> 3, c4 = idx & 7;                   \
      ra3 = *(const float4*)&A[(size_t)(m0 + row) * Dn + (kk) + c4 * 4]; }   \
  } else {                                                                   \
    { int idx = t;       int row = idx >> 2, c16 = idx & 3;                  \
      ha0 = *(const uint4*)&g_ctxh[(size_t)(m0 + row) * Dn + (kk) + c16*8];} \
    { int idx = t + 256; int row = idx >> 2, c16 = idx & 3;                  \
      ha1 = *(const uint4*)&g_ctxh[(size_t)(m0 + row) * Dn + (kk) + c16*8];} \
  }

#define G_LOAD_B(kk)                                                         \
  { int idx = t;       int kp = idx >> 5, n4 = (idx & 31) * 4;               \
    rb0 = *(const float4*)&W[(size_t)((kk) + 2*kp)     * NDIM + n0 + n4];    \
    rb1 = *(const float4*)&W[(size_t)((kk) + 2*kp + 1) * NDIM + n0 + n4]; }  \
  { int idx = t + 256; int kp = idx >> 5, n4 = (idx & 31) * 4;               \
    rb2 = *(const float4*)&W[(size_t)((kk) + 2*kp)     * NDIM + n0 + n4];    \
    rb3 = *(const float4*)&W[(size_t)((kk) + 2*kp + 1) * NDIM + n0 + n4]; }

#define G_STORE_A()                                                          \
  if (MODE == 1) {                                                           \
    { int idx = t;       int row = idx >> 3, c4 = idx & 7; unsigned u0, u1;  \
      F22H(u0, ra0.x, ra0.y); F22H(u1, ra0.z, ra0.w);                        \
      *(uint2*)&As2[row][c4 * 2] = make_uint2(u0, u1); }                     \
    { int idx = t + 256; int row = idx >> 3, c4 = idx & 7; unsigned u0, u1;  \
      F22H(u0, ra1.x, ra1.y); F22H(u1, ra1.z, ra1.w);                        \
      *(uint2*)&As2[row][c4 * 2] = make_uint2(u0, u1); }                     \
    { int idx = t + 512; int row = idx >> 3, c4 = idx & 7; unsigned u0, u1;  \
      F22H(u0, ra2.x, ra2.y); F22H(u1, ra2.z, ra2.w);                        \
      *(uint2*)&As2[row][c4 * 2] = make_uint2(u0, u1); }                     \
    { int idx = t + 768; int row = idx >> 3, c4 = idx & 7; unsigned u0, u1;  \
      F22H(u0, ra3.x, ra3.y); F22H(u1, ra3.z, ra3.w);                        \
      *(uint2*)&As2[row][c4 * 2] = make_uint2(u0, u1); }                     \
  } else {                                                                   \
    { int idx = t;       int row = idx >> 2, c16 = idx & 3;                  \
      *(uint4*)&As2[row][c16 * 4] = ha0; }                                   \
    { int idx = t + 256; int row = idx >> 2, c16 = idx & 3;                  \
      *(uint4*)&As2[row][c16 * 4] = ha1; }                                   \
  }

#define G_STORE_B()                                                          \
  { int idx = t;       int kp = idx >> 5, n4 = (idx & 31) * 4;               \
    unsigned u0, u1, u2, u3;                                                 \
    F22H(u0, rb0.x, rb1.x); F22H(u1, rb0.y, rb1.y);                          \
    F22H(u2, rb0.z, rb1.z); F22H(u3, rb0.w, rb1.w);                          \
    *(uint4*)&Bs2[kp][n4] = make_uint4(u0, u1, u2, u3); }                    \
  { int idx = t + 256; int kp = idx >> 5, n4 = (idx & 31) * 4;               \
    unsigned u0, u1, u2, u3;                                                 \
    F22H(u0, rb2.x, rb3.x); F22H(u1, rb2.y, rb3.y);                          \
    F22H(u2, rb2.z, rb3.z); F22H(u3, rb2.w, rb3.w);                          \
    *(uint4*)&Bs2[kp][n4] = make_uint4(u0, u1, u2, u3); }

  float acc[2][8][4];
#pragma unroll
  for (int mt = 0; mt < 2; mt++)
#pragma unroll
    for (int nt = 0; nt < 8; nt++)
#pragma unroll
      for (int j = 0; j < 4; j++) acc[mt][nt][j] = 0.0f;

  G_LOAD_A(0)
  G_LOAD_B(0)
  G_STORE_A()
  G_STORE_B()
  __syncthreads();

  for (int it = 0; it < Dn / 32; it++) {
    if (it + 1 < Dn / 32) {
      const int kn = (it + 1) * 32;
      G_LOAD_A(kn)
      G_LOAD_B(kn)
    }

#pragma unroll
    for (int ks = 0; ks < 2; ks++) {       // two k16 steps per BK=32
      const int pb = ks * 8;               // pair base
      unsigned a00, a01, a02, a03, a10, a11, a12, a13;
      {
        const int r = wm * 32 + lq;
        a00 = As2[r][pb + lt];
        a01 = As2[r + 8][pb + lt];
        a02 = As2[r][pb + lt + 4];
        a03 = As2[r + 8][pb + lt + 4];
        a10 = As2[r + 16][pb + lt];
        a11 = As2[r + 24][pb + lt];
        a12 = As2[r + 16][pb + lt + 4];
        a13 = As2[r + 24][pb + lt + 4];
      }
#pragma unroll
      for (int nt = 0; nt < 8; nt++) {
        const int n  = wn * 64 + nt * 8 + lq;
        unsigned b0 = Bs2[pb + lt][n];
        unsigned b1 = Bs2[pb + lt + 4][n];
        MMA_F16(acc[0][nt][0], acc[0][nt][1], acc[0][nt][2], acc[0][nt][3],
                a00, a01, a02, a03, b0, b1);
        MMA_F16(acc[1][nt][0], acc[1][nt][1], acc[1][nt][2], acc[1][nt][3],
                a10, a11, a12, a13, b0, b1);
      }
    }
    __syncthreads();
    if (it + 1 < Dn / 32) {
      G_STORE_A()
      G_STORE_B()
      __syncthreads();
    }
  }

  // Epilogue
#pragma unroll
  for (int mt = 0; mt < 2; mt++) {
    const int r0 = m0 + wm * 32 + mt * 16 + lq;
#pragma unroll
    for (int nt = 0; nt < 8; nt++) {
      const int c0 = n0 + wn * 64 + nt * 8 + lt * 2;
      float v0 = acc[mt][nt][0] + bias[c0];
      float v1 = acc[mt][nt][1] + bias[c0 + 1];
      float v2 = acc[mt][nt][2] + bias[c0];
      float v3 = acc[mt][nt][3] + bias[c0 + 1];
      if (MODE == 0) {
        g_proj[(size_t)r0 * Dn + c0]           = v0;
        g_proj[(size_t)r0 * Dn + c0 + 1]       = v1;
        g_proj[(size_t)(r0 + 8) * Dn + c0]     = v2;
        g_proj[(size_t)(r0 + 8) * Dn + c0 + 1] = v3;
      } else {
        scatter_qkv(r0, c0, v0);
        scatter_qkv(r0, c0 + 1, v1);
        scatter_qkv(r0 + 8, c0, v2);
        scatter_qkv(r0 + 8, c0 + 1, v3);
      }
    }
  }
}

// ---------------------------------------------------------------------------
// Flash attention, fp16 mma. Block = 128 queries of one (b,h), key tiles 64.
// 256 threads, 8 warps (4x2), warp tiles 32x32.
// Smem (uint32 words unless noted), all pair-interleaved stride 36:
//   Qs2[128][36]  Ps2[128][36]  Ks2[64][36]  Vs2[64][36]
//   Sraw fp32 [128][68], crow fp32 [128]
// ---------------------------------------------------------------------------
#define QS_OFF 0
#define PS_OFF 4608
#define KS_OFF 9216
#define VS_OFF 11520
#define SR_OFF 13824   // fp32 region, 128*68
#define CR_OFF 22528   // fp32, 128
#define ATTN_SMEM_WORDS 22656

__global__ __launch_bounds__(256) void attn_f16_kernel() {
  extern __shared__ __align__(16) unsigned smu[];
  float* Sraw = (float*)(smu + SR_OFF);
  float* crow = (float*)(smu + CR_OFF);

  const int t    = threadIdx.x;
  const int lane = t & 31;
  const int lq   = lane >> 2;
  const int lt   = lane & 3;
  const int warp = t >> 5;
  const int wm   = warp >> 1;  // 0..3
  const int wn   = warp & 1;   // 0..1
  const int b    = blockIdx.z;
  const int h    = blockIdx.y;
  const int s0   = blockIdx.x * 128;

  const size_t baseQK = (size_t)(b * Hn + h) * Sn * HDn;  // q,k: [S][Hd]
  const size_t baseV  = (size_t)(b * Hn + h) * HDn * Sn;  // v:   [Hd][S]

  // Load Q tile (pre-scaled at QKV epilogue): pure 16B copies.
#pragma unroll
  for (int i = 0; i < 4; i++) {
    int idx = t + i * 256;            // 0..1023
    int row = idx >> 3, c16 = idx & 7;
    *(uint4*)&smu[QS_OFF + row * 36 + c16 * 4] =
        *(const uint4*)&g_qh[baseQK + (size_t)(s0 + row) * HDn + c16 * 8];
  }

  float m_run = -INFINITY, l_run = 0.0f;

  float acc_o[2][4][4];
#pragma unroll
  for (int mt = 0; mt < 2; mt++)
#pragma unroll
    for (int nt = 0; nt < 4; nt++)
#pragma unroll
      for (int j = 0; j < 4; j++) acc_o[mt][nt][j] = 0.0f;

  for (int k0 = 0; k0 < Sn; k0 += 64) {
    __syncthreads();  // protect Ks2/Vs2/Ps2 reuse from previous iteration
    // K tile [key][d] and V tile [d][key]: raw 16B copies.
#pragma unroll
    for (int i = 0; i < 2; i++) {
      int idx = t + i * 256;          // 0..511
      int row = idx >> 3, c16 = idx & 7;
      *(uint4*)&smu[KS_OFF + row * 36 + c16 * 4] =
          *(const uint4*)&g_kh[baseQK + (size_t)(k0 + row) * HDn + c16 * 8];
      *(uint4*)&smu[VS_OFF + row * 36 + c16 * 4] =
          *(const uint4*)&g_vh[baseV + (size_t)row * Sn + k0 + c16 * 8];
    }
    __syncthreads();

    // S = Q K^T  (A=Qs2 [q][d], B=Ks2 [key][d] col-layout)
    float accs[2][4][4];
#pragma unroll
    for (int mt = 0; mt < 2; mt++)
#pragma unroll
      for (int nt = 0; nt < 4; nt++)
#pragma unroll
        for (int j = 0; j < 4; j++) accs[mt][nt][j] = 0.0f;

#pragma unroll
    for (int ks = 0; ks < 4; ks++) {      // d = 64 -> 4 k16 steps
      const int pb = ks * 8;
      unsigned a00, a01, a02, a03, a10, a11, a12, a13;
      {
        const int r = wm * 32 + lq;
        a00 = smu[QS_OFF + r * 36 + pb + lt];
        a01 = smu[QS_OFF + (r + 8) * 36 + pb + lt];
        a02 = smu[QS_OFF + r * 36 + pb + lt + 4];
        a03 = smu[QS_OFF + (r + 8) * 36 + pb + lt + 4];
        a10 = smu[QS_OFF + (r + 16) * 36 + pb + lt];
        a11 = smu[QS_OFF + (r + 24) * 36 + pb + lt];
        a12 = smu[QS_OFF + (r + 16) * 36 + pb + lt + 4];
        a13 = smu[QS_OFF + (r + 24) * 36 + pb + lt + 4];
      }
#pragma unroll
      for (int nt = 0; nt < 4; nt++) {
        const int n = wn * 32 + nt * 8 + lq;     // key col
        unsigned b0 = smu[KS_OFF + n * 36 + pb + lt];
        unsigned b1 = smu[KS_OFF + n * 36 + pb + lt + 4];
        MMA_F16(accs[0][nt][0], accs[0][nt][1], accs[0][nt][2], accs[0][nt][3],
                a00, a01, a02, a03, b0, b1);
        MMA_F16(accs[1][nt][0], accs[1][nt][1], accs[1][nt][2], accs[1][nt][3],
                a10, a11, a12, a13, b0, b1);
      }
    }

    // Raw fp32 scores to Sraw
#pragma unroll
    for (int mt = 0; mt < 2; mt++) {
      int r = wm * 32 + mt * 16 + lq;
#pragma unroll
      for (int nt = 0; nt < 4; nt++) {
        int c = wn * 32 + nt * 8 + lt * 2;
        Sraw[r * 68 + c]           = accs[mt][nt][0];
        Sraw[r * 68 + c + 1]       = accs[mt][nt][1];
        Sraw[(r + 8) * 68 + c]     = accs[mt][nt][2];
        Sraw[(r + 8) * 68 + c + 1] = accs[mt][nt][3];
      }
    }
    __syncthreads();

    // Online softmax: row = t>>1, half = t&1 owns 32 cols. Writes half2 pairs.
    {
      const int row = t >> 1;
      const int cb  = (t & 1) * 32;
      float mx = -INFINITY;
#pragma unroll
      for (int j = 0; j < 32; j += 4) {
        float4 v4 = *(float4*)&Sraw[row * 68 + cb + j];
        mx = fmaxf(mx, fmaxf(fmaxf(v4.x, v4.y), fmaxf(v4.z, v4.w)));
      }
      mx = fmaxf(mx, __shfl_xor_sync(0xffffffffu, mx, 1));
      const float mnew = fmaxf(m_run, mx);
      const float corr = __expf(m_run - mnew);
      float s = 0.0f;
#pragma unroll
      for (int j = 0; j < 32; j += 4) {
        float4 v4 = *(float4*)&Sraw[row * 68 + cb + j];
        float p0 = __expf(v4.x - mnew);
        float p1 = __expf(v4.y - mnew);
        float p2 = __expf(v4.z - mnew);
        float p3 = __expf(v4.w - mnew);
        s += (p0 + p1) + (p2 + p3);
        unsigned u0, u1;
        F22H(u0, p0, p1);
        F22H(u1, p2, p3);
        *(uint2*)&smu[PS_OFF + row * 36 + (cb + j) / 2] = make_uint2(u0, u1);
      }
      s += __shfl_xor_sync(0xffffffffu, s, 1);
      l_run = l_run * corr + s;
      m_run = mnew;
      if (!(t & 1)) crow[row] = corr;
    }
    __syncthreads();

    // Scale accumulators by correction, then O += P @ V
#pragma unroll
    for (int mt = 0; mt < 2; mt++) {
      int r = wm * 32 + mt * 16 + lq;
      float c0 = crow[r], c8 = crow[r + 8];
#pragma unroll
      for (int nt = 0; nt < 4; nt++) {
        acc_o[mt][nt][0] *= c0;
        acc_o[mt][nt][1] *= c0;
        acc_o[mt][nt][2] *= c8;
        acc_o[mt][nt][3] *= c8;
      }
    }

#pragma unroll
    for (int ks = 0; ks < 4; ks++) {      // key = 64 -> 4 k16 steps
      const int pb = ks * 8;
      unsigned a00, a01, a02, a03, a10, a11, a12, a13;
      {
        const int r = wm * 32 + lq;
        a00 = smu[PS_OFF + r * 36 + pb + lt];
        a01 = smu[PS_OFF + (r + 8) * 36 + pb + lt];
        a02 = smu[PS_OFF + r * 36 + pb + lt + 4];
        a03 = smu[PS_OFF + (r + 8) * 36 + pb + lt + 4];
        a10 = smu[PS_OFF + (r + 16) * 36 + pb + lt];
        a11 = smu[PS_OFF + (r + 24) * 36 + pb + lt];
        a12 = smu[PS_OFF + (r + 16) * 36 + pb + lt + 4];
        a13 = smu[PS_OFF + (r + 24) * 36 + pb + lt + 4];
      }
#pragma unroll
      for (int nt = 0; nt < 4; nt++) {
        const int n = wn * 32 + nt * 8 + lq;     // d col
        unsigned b0 = smu[VS_OFF + n * 36 + pb + lt];
        unsigned b1 = smu[VS_OFF + n * 36 + pb + lt + 4];
        MMA_F16(acc_o[0][nt][0], acc_o[0][nt][1], acc_o[0][nt][2],
                acc_o[0][nt][3], a00, a01, a02, a03, b0, b1);
        MMA_F16(acc_o[1][nt][0], acc_o[1][nt][1], acc_o[1][nt][2],
                acc_o[1][nt][3], a10, a11, a12, a13, b0, b1);
      }
    }
  }

  // Final normalization: publish 1/l per row, write half context
  if (!(t & 1)) crow[t >> 1] = 1.0f / l_run;
  __syncthreads();

#pragma unroll
  for (int mt = 0; mt < 2; mt++) {
    const int r    = wm * 32 + mt * 16 + lq;
    const float i0 = crow[r];
    const float i8 = crow[r + 8];
#pragma unroll
    for (int nt = 0; nt < 4; nt++) {
      const int c = wn * 32 + nt * 8 + lt * 2;
      unsigned u0, u8;
      F22H(u0, acc_o[mt][nt][0] * i0, acc_o[mt][nt][1] * i0);
      F22H(u8, acc_o[mt][nt][2] * i8, acc_o[mt][nt][3] * i8);
      *(unsigned*)&g_ctxh[(size_t)(b * Sn + s0 + r) * Dn + h * HDn + c] = u0;
      *(unsigned*)&g_ctxh[(size_t)(b * Sn + s0 + r + 8) * Dn + h * HDn + c] = u8;
    }
  }
}

// ---------------------------------------------------------------------------
// Residual + LayerNorm (fp32, unchanged)
// ---------------------------------------------------------------------------
__device__ __forceinline__ float block_sum(float v, float* red) {
#pragma unroll
  for (int o = 16; o; o >>= 1) v += __shfl_xor_sync(0xffffffffu, v, o);
  if ((threadIdx.x & 31) == 0) red[threadIdx.x >> 5] = v;
  __syncthreads();
  float tot = red[0] + red[1] + red[2] + red[3] +
              red[4] + red[5] + red[6] + red[7];
  __syncthreads();
  return tot;
}

__global__ __launch_bounds__(256) void ln_kernel(
    const float* __restrict__ x, const float* __restrict__ gamma,
    const float* __restrict__ beta, float* __restrict__ out) {
  __shared__ float red[8];
  const int row = blockIdx.x;
  const int c   = threadIdx.x * 4;

  float4 y  = *(const float4*)&g_proj[(size_t)row * Dn + c];
  float4 xv = *(const float4*)&x[(size_t)row * Dn + c];
  y.x += xv.x; y.y += xv.y; y.z += xv.z; y.w += xv.w;

  float tot = block_sum(y.x + y.y + y.z + y.w, red);
  const float mu = tot * (1.0f / Dn);

  float dx = y.x - mu, dy = y.y - mu, dz = y.z - mu, dw = y.w - mu;
  float sq = block_sum(dx * dx + dy * dy + dz * dz + dw * dw, red);
  const float var = sq * (1.0f / Dn);
  const float r = rsqrtf(var + 1e-5f);

  float4 g  = *(const float4*)&gamma[c];
  float4 bt = *(const float4*)&beta[c];
  float4 o;
  o.x = dx * r * g.x + bt.x;
  o.y = dy * r * g.y + bt.y;
  o.z = dz * r * g.z + bt.z;
  o.w = dw * r * g.w + bt.w;
  *(float4*)&out[(size_t)row * Dn + c] = o;
}

// ---------------------------------------------------------------------------
// Launch — only harness-provided pointers cross the host/device boundary.
// ---------------------------------------------------------------------------
extern "C" void kernel_launch(void* const* d_in, const int* in_sizes, int n_in,
                              void* d_out, int out_size) {
  (void)in_sizes; (void)n_in; (void)out_size;
  const float* x     = (const float*)d_in[0];
  const float* W_qkv = (const float*)d_in[1];
  const float* b_qkv = (const float*)d_in[2];
  const float* W_out = (const float*)d_in[3];
  const float* b_out = (const float*)d_in[4];
  const float* gamma = (const float*)d_in[5];
  const float* beta  = (const float*)d_in[6];
  float* out = (float*)d_out;

  const int attn_smem = ATTN_SMEM_WORDS * 4;  // 90624 B
  cudaFuncSetAttribute(attn_f16_kernel,
                       cudaFuncAttributeMaxDynamicSharedMemorySize, attn_smem);

  gemm_f16_kernel<N3, 1><<<dim3(N3 / 128, (Bn * Sn) / 128), 256>>>(
      x, W_qkv, b_qkv);
  attn_f16_kernel<<<dim3(Sn / 128, Hn, Bn), 256, attn_smem>>>();
  gemm_f16_kernel<Dn, 0><<<dim3(Dn / 128, (Bn * Sn) / 128), 256>>>(
      x, W_out, b_out);
  ln_kernel<<<Bn * Sn, 256>>>(x, gamma, beta, out);
}

// round 7
// speedup vs baseline: 4.4398x; 1.1189x over previous
#include <cuda_runtime.h>
#include <cuda_fp16.h>
#include <math.h>

// Problem constants
#define Bn 4
#define Sn 2048
#define Dn 1024
#define Hn 16
#define HDn 64
#define N3 3072   // 3*Dn

// ---------------------------------------------------------------------------
// Device scratch (referenced ONLY in device code — R5 ATS lesson)
// g_qh : [B, H, S, Hd] half, PRE-SCALED by 1/8
// g_kh : [B, H, S, Hd] half
// g_vh : [B, H, Hd, S] half (transposed: PV mma B operand)
// ---------------------------------------------------------------------------
__device__ __half g_qh[(size_t)Bn * Hn * Sn * HDn];
__device__ __half g_kh[(size_t)Bn * Hn * Sn * HDn];
__device__ __half g_vh[(size_t)Bn * Hn * HDn * Sn];
__device__ __half g_ctxh[(size_t)Bn * Sn * Dn];
__device__ float  g_proj[(size_t)Bn * Sn * Dn];

// Pack two floats -> f16x2 (lo = first elem, hi = second).
#define F22H(u, lo, hi)                                                      \
  asm("cvt.rn.f16x2.f32 %0, %1, %2;" : "=r"(u) : "f"(hi), "f"(lo))

// fp16 mma, fp32 accumulate; macro so operands bind to lvalues (no lmem).
#define MMA_F16(c0, c1, c2, c3, a0, a1, a2, a3, b0, b1)                      \
  asm volatile(                                                              \
      "mma.sync.aligned.m16n8k16.row.col.f32.f16.f16.f32 "                   \
      "{%0,%1,%2,%3},{%4,%5,%6,%7},{%8,%9},{%0,%1,%2,%3};"                   \
      : "+f"(c0), "+f"(c1), "+f"(c2), "+f"(c3)                               \
      : "r"(a0), "r"(a1), "r"(a2), "r"(a3), "r"(b0), "r"(b1))

// ---------------------------------------------------------------------------
// QKV scatter epilogue helper (half outputs; Q pre-scaled by 0.125)
// ---------------------------------------------------------------------------
__device__ __forceinline__ void scatter_qkv(int m, int n, float val) {
  const int sec = n >> 10;            // 0=Q,1=K,2=V
  const int h   = (n & 1023) >> 6;
  const int hd  = n & 63;
  const int b   = m >> 11;
  const int s   = m & 2047;
  if (sec == 0)
    g_qh[((size_t)(b * Hn + h) * Sn + s) * HDn + hd] =
        __float2half_rn(val * 0.125f);
  else if (sec == 1)
    g_kh[((size_t)(b * Hn + h) * Sn + s) * HDn + hd] = __float2half_rn(val);
  else
    g_vh[((size_t)(b * Hn + h) * HDn + hd) * Sn + s] = __float2half_rn(val);
}

// ---------------------------------------------------------------------------
// FP16 GEMM: C[8192, NDIM] = Asrc[8192,1024] @ W[1024,NDIM] + bias
// Block 128x128, BK=32, 256 threads, 8 warps (4x2), warp tile 32x64.
// DOUBLE-BUFFERED smem (1 sync per K-step).
// MODE 0: Asrc = g_ctxh (half copy), write g_proj. MODE 1: Asrc = x, scatter.
// ---------------------------------------------------------------------------
template <int NDIM, int MODE>
__global__ __launch_bounds__(256) void gemm_f16_kernel(
    const float* __restrict__ A, const float* __restrict__ W,
    const float* __restrict__ bias) {
  __shared__ __align__(16) unsigned As2[2][128][20];
  __shared__ __align__(16) unsigned Bs2[2][16][136];

  const int t    = threadIdx.x;
  const int lane = t & 31;
  const int lq   = lane >> 2;
  const int lt   = lane & 3;
  const int warp = t >> 5;
  const int wm   = warp >> 1;
  const int wn   = warp & 1;
  const int n0   = blockIdx.x * 128;
  const int m0   = blockIdx.y * 128;

  float4 ra0, ra1, ra2, ra3;
  uint4  ha0, ha1;
  float4 rb0, rb1, rb2, rb3;

#define G_LOAD_A(kk)                                                         \
  if (MODE == 1) {                                                           \
    { int idx = t;       int row = idx >> 3, c4 = idx & 7;                   \
      ra0 = *(const float4*)&A[(size_t)(m0 + row) * Dn + (kk) + c4 * 4]; }   \
    { int idx = t + 256; int row = idx >> 3, c4 = idx & 7;                   \
      ra1 = *(const float4*)&A[(size_t)(m0 + row) * Dn + (kk) + c4 * 4]; }   \
    { int idx = t + 512; int row = idx >> 3, c4 = idx & 7;                   \
      ra2 = *(const float4*)&A[(size_t)(m0 + row) * Dn + (kk) + c4 * 4]; }   \
    { int idx = t + 768; int row = idx >> 3, c4 = idx & 7;                   \
      ra3 = *(const float4*)&A[(size_t)(m0 + row) * Dn + (kk) + c4 * 4]; }   \
  } else {                                                                   \
    { int idx = t;       int row = idx >> 2, c16 = idx & 3;                  \
      ha0 = *(const uint4*)&g_ctxh[(size_t)(m0 + row) * Dn + (kk) + c16*8];} \
    { int idx = t + 256; int row = idx >> 2, c16 = idx & 3;                  \
      ha1 = *(const uint4*)&g_ctxh[(size_t)(m0 + row) * Dn + (kk) + c16*8];} \
  }

#define G_LOAD_B(kk)                                                         \
  { int idx = t;       int kp = idx >> 5, n4 = (idx & 31) * 4;               \
    rb0 = *(const float4*)&W[(size_t)((kk) + 2*kp)     * NDIM + n0 + n4];    \
    rb1 = *(const float4*)&W[(size_t)((kk) + 2*kp + 1) * NDIM + n0 + n4]; }  \
  { int idx = t + 256; int kp = idx >> 5, n4 = (idx & 31) * 4;               \
    rb2 = *(const float4*)&W[(size_t)((kk) + 2*kp)     * NDIM + n0 + n4];    \
    rb3 = *(const float4*)&W[(size_t)((kk) + 2*kp + 1) * NDIM + n0 + n4]; }

#define G_STORE_A(bb)                                                        \
  if (MODE == 1) {                                                           \
    { int idx = t;       int row = idx >> 3, c4 = idx & 7; unsigned u0, u1;  \
      F22H(u0, ra0.x, ra0.y); F22H(u1, ra0.z, ra0.w);                        \
      *(uint2*)&As2[bb][row][c4 * 2] = make_uint2(u0, u1); }                 \
    { int idx = t + 256; int row = idx >> 3, c4 = idx & 7; unsigned u0, u1;  \
      F22H(u0, ra1.x, ra1.y); F22H(u1, ra1.z, ra1.w);                        \
      *(uint2*)&As2[bb][row][c4 * 2] = make_uint2(u0, u1); }                 \
    { int idx = t + 512; int row = idx >> 3, c4 = idx & 7; unsigned u0, u1;  \
      F22H(u0, ra2.x, ra2.y); F22H(u1, ra2.z, ra2.w);                        \
      *(uint2*)&As2[bb][row][c4 * 2] = make_uint2(u0, u1); }                 \
    { int idx = t + 768; int row = idx >> 3, c4 = idx & 7; unsigned u0, u1;  \
      F22H(u0, ra3.x, ra3.y); F22H(u1, ra3.z, ra3.w);                        \
      *(uint2*)&As2[bb][row][c4 * 2] = make_uint2(u0, u1); }                 \
  } else {                                                                   \
    { int idx = t;       int row = idx >> 2, c16 = idx & 3;                  \
      *(uint4*)&As2[bb][row][c16 * 4] = ha0; }                               \
    { int idx = t + 256; int row = idx >> 2, c16 = idx & 3;                  \
      *(uint4*)&As2[bb][row][c16 * 4] = ha1; }                               \
  }

#define G_STORE_B(bb)                                                        \
  { int idx = t;       int kp = idx >> 5, n4 = (idx & 31) * 4;               \
    unsigned u0, u1, u2, u3;                                                 \
    F22H(u0, rb0.x, rb1.x); F22H(u1, rb0.y, rb1.y);                          \
    F22H(u2, rb0.z, rb1.z); F22H(u3, rb0.w, rb1.w);                          \
    *(uint4*)&Bs2[bb][kp][n4] = make_uint4(u0, u1, u2, u3); }                \
  { int idx = t + 256; int kp = idx >> 5, n4 = (idx & 31) * 4;               \
    unsigned u0, u1, u2, u3;                                                 \
    F22H(u0, rb2.x, rb3.x); F22H(u1, rb2.y, rb3.y);                          \
    F22H(u2, rb2.z, rb3.z); F22H(u3, rb2.w, rb3.w);                          \
    *(uint4*)&Bs2[bb][kp][n4] = make_uint4(u0, u1, u2, u3); }

  float acc[2][8][4];
#pragma unroll
  for (int mt = 0; mt < 2; mt++)
#pragma unroll
    for (int nt = 0; nt < 8; nt++)
#pragma unroll
      for (int j = 0; j < 4; j++) acc[mt][nt][j] = 0.0f;

  G_LOAD_A(0)
  G_LOAD_B(0)
  G_STORE_A(0)
  G_STORE_B(0)
  __syncthreads();

  for (int it = 0; it < Dn / 32; it++) {
    const int bb = it & 1;
    if (it + 1 < Dn / 32) {
      const int kn = (it + 1) * 32;
      G_LOAD_A(kn)
      G_LOAD_B(kn)
    }

#pragma unroll
    for (int ks = 0; ks < 2; ks++) {
      const int pb = ks * 8;
      unsigned a00, a01, a02, a03, a10, a11, a12, a13;
      {
        const int r = wm * 32 + lq;
        a00 = As2[bb][r][pb + lt];
        a01 = As2[bb][r + 8][pb + lt];
        a02 = As2[bb][r][pb + lt + 4];
        a03 = As2[bb][r + 8][pb + lt + 4];
        a10 = As2[bb][r + 16][pb + lt];
        a11 = As2[bb][r + 24][pb + lt];
        a12 = As2[bb][r + 16][pb + lt + 4];
        a13 = As2[bb][r + 24][pb + lt + 4];
      }
#pragma unroll
      for (int nt = 0; nt < 8; nt++) {
        const int n  = wn * 64 + nt * 8 + lq;
        unsigned b0 = Bs2[bb][pb + lt][n];
        unsigned b1 = Bs2[bb][pb + lt + 4][n];
        MMA_F16(acc[0][nt][0], acc[0][nt][1], acc[0][nt][2], acc[0][nt][3],
                a00, a01, a02, a03, b0, b1);
        MMA_F16(acc[1][nt][0], acc[1][nt][1], acc[1][nt][2], acc[1][nt][3],
                a10, a11, a12, a13, b0, b1);
      }
    }
    if (it + 1 < Dn / 32) {
      G_STORE_A(1 - bb)
      G_STORE_B(1 - bb)
    }
    __syncthreads();
  }

  // Epilogue
#pragma unroll
  for (int mt = 0; mt < 2; mt++) {
    const int r0 = m0 + wm * 32 + mt * 16 + lq;
#pragma unroll
    for (int nt = 0; nt < 8; nt++) {
      const int c0 = n0 + wn * 64 + nt * 8 + lt * 2;
      float v0 = acc[mt][nt][0] + bias[c0];
      float v1 = acc[mt][nt][1] + bias[c0 + 1];
      float v2 = acc[mt][nt][2] + bias[c0];
      float v3 = acc[mt][nt][3] + bias[c0 + 1];
      if (MODE == 0) {
        g_proj[(size_t)r0 * Dn + c0]           = v0;
        g_proj[(size_t)r0 * Dn + c0 + 1]       = v1;
        g_proj[(size_t)(r0 + 8) * Dn + c0]     = v2;
        g_proj[(size_t)(r0 + 8) * Dn + c0 + 1] = v3;
      } else {
        scatter_qkv(r0, c0, v0);
        scatter_qkv(r0, c0 + 1, v1);
        scatter_qkv(r0 + 8, c0, v2);
        scatter_qkv(r0 + 8, c0 + 1, v3);
      }
    }
  }
}

// ---------------------------------------------------------------------------
// Flash attention, FA2-style: 8 warps x 16-row stripes, softmax fully in
// registers (QK^T C-fragment == PV A-fragment), K/V double-buffered in smem.
// Smem words: Qs[128][36]=4608, KV buf x2 (K 64x36 + V 64x36 = 4608 each).
// Total 13824 words = 55296 B. One __syncthreads per key tile.
// ---------------------------------------------------------------------------
#define AT_KV0 4608
#define ATTN_SMEM_WORDS 13824

#define ATT_LOAD(kk)                                                         \
  { int idx = t;       int row = idx >> 3, c16 = idx & 7;                    \
    kr0 = *(const uint4*)&g_kh[baseQK + (size_t)((kk) + row) * HDn + c16*8]; \
    vr0 = *(const uint4*)&g_vh[baseV + (size_t)row * Sn + (kk) + c16 * 8]; } \
  { int idx = t + 256; int row = idx >> 3, c16 = idx & 7;                    \
    kr1 = *(const uint4*)&g_kh[baseQK + (size_t)((kk) + row) * HDn + c16*8]; \
    vr1 = *(const uint4*)&g_vh[baseV + (size_t)row * Sn + (kk) + c16 * 8]; }

#define ATT_STORE(base)                                                      \
  { int idx = t;       int row = idx >> 3, c16 = idx & 7;                    \
    *(uint4*)&smu[(base) + row * 36 + c16 * 4]        = kr0;                 \
    *(uint4*)&smu[(base) + 2304 + row * 36 + c16 * 4] = vr0; }               \
  { int idx = t + 256; int row = idx >> 3, c16 = idx & 7;                    \
    *(uint4*)&smu[(base) + row * 36 + c16 * 4]        = kr1;                 \
    *(uint4*)&smu[(base) + 2304 + row * 36 + c16 * 4] = vr1; }

__global__ __launch_bounds__(256) void attn_f16_kernel() {
  extern __shared__ __align__(16) unsigned smu[];

  const int t    = threadIdx.x;
  const int lane = t & 31;
  const int lq   = lane >> 2;
  const int lt   = lane & 3;
  const int warp = t >> 5;
  const int rw   = warp * 16;           // warp's query-row stripe
  const int b    = blockIdx.z;
  const int h    = blockIdx.y;
  const int sQ   = blockIdx.x * 128;

  const size_t baseQK = (size_t)(b * Hn + h) * Sn * HDn;  // q,k: [S][Hd]
  const size_t baseV  = (size_t)(b * Hn + h) * HDn * Sn;  // v:   [Hd][S]

  uint4 kr0, kr1, vr0, vr1;

  // Q tile (pre-scaled): 16B copies into pair-interleaved [q][dpair] stride 36
#pragma unroll
  for (int i = 0; i < 4; i++) {
    int idx = t + i * 256;
    int row = idx >> 3, c16 = idx & 7;
    *(uint4*)&smu[row * 36 + c16 * 4] =
        *(const uint4*)&g_qh[baseQK + (size_t)(sQ + row) * HDn + c16 * 8];
  }

  ATT_LOAD(0)
  ATT_STORE(AT_KV0)
  __syncthreads();

  float m0 = -INFINITY, m1 = -INFINITY, l0 = 0.0f, l1 = 0.0f;
  float o[8][4];
#pragma unroll
  for (int nd = 0; nd < 8; nd++)
#pragma unroll
    for (int j = 0; j < 4; j++) o[nd][j] = 0.0f;

  for (int it = 0; it < Sn / 64; it++) {
    const int ksb = AT_KV0 + (it & 1) * 4608;
    const int vsb = ksb + 2304;
    if (it + 1 < Sn / 64) ATT_LOAD((it + 1) * 64)

    // S = Q K^T : warp computes 16x64 (8 n-tiles)
    float sa[8][4];
#pragma unroll
    for (int nt = 0; nt < 8; nt++)
#pragma unroll
      for (int j = 0; j < 4; j++) sa[nt][j] = 0.0f;

#pragma unroll
    for (int ks = 0; ks < 4; ks++) {
      unsigned a0, a1, a2, a3;
      {
        const int r = rw + lq;
        a0 = smu[r * 36 + ks * 8 + lt];
        a1 = smu[(r + 8) * 36 + ks * 8 + lt];
        a2 = smu[r * 36 + ks * 8 + lt + 4];
        a3 = smu[(r + 8) * 36 + ks * 8 + lt + 4];
      }
#pragma unroll
      for (int nt = 0; nt < 8; nt++) {
        const int kc = nt * 8 + lq;          // key column
        unsigned b0 = smu[ksb + kc * 36 + ks * 8 + lt];
        unsigned b1 = smu[ksb + kc * 36 + ks * 8 + lt + 4];
        MMA_F16(sa[nt][0], sa[nt][1], sa[nt][2], sa[nt][3],
                a0, a1, a2, a3, b0, b1);
      }
    }

    // Register softmax. Row r0 = rw+lq lives in sa[*][0..1] over 4 lt lanes;
    // row r1 = rw+lq+8 in sa[*][2..3].
    float mx0 = -INFINITY, mx1 = -INFINITY;
#pragma unroll
    for (int nt = 0; nt < 8; nt++) {
      mx0 = fmaxf(mx0, fmaxf(sa[nt][0], sa[nt][1]));
      mx1 = fmaxf(mx1, fmaxf(sa[nt][2], sa[nt][3]));
    }
    mx0 = fmaxf(mx0, __shfl_xor_sync(0xffffffffu, mx0, 1));
    mx0 = fmaxf(mx0, __shfl_xor_sync(0xffffffffu, mx0, 2));
    mx1 = fmaxf(mx1, __shfl_xor_sync(0xffffffffu, mx1, 1));
    mx1 = fmaxf(mx1, __shfl_xor_sync(0xffffffffu, mx1, 2));
    const float mn0 = fmaxf(m0, mx0);
    const float mn1 = fmaxf(m1, mx1);
    const float cr0 = __expf(m0 - mn0);
    const float cr1 = __expf(m1 - mn1);
    m0 = mn0; m1 = mn1;

    float sum0 = 0.0f, sum1 = 0.0f;
#pragma unroll
    for (int nt = 0; nt < 8; nt++) {
      sa[nt][0] = __expf(sa[nt][0] - mn0);
      sa[nt][1] = __expf(sa[nt][1] - mn0);
      sa[nt][2] = __expf(sa[nt][2] - mn1);
      sa[nt][3] = __expf(sa[nt][3] - mn1);
      sum0 += sa[nt][0] + sa[nt][1];
      sum1 += sa[nt][2] + sa[nt][3];
    }
    sum0 += __shfl_xor_sync(0xffffffffu, sum0, 1);
    sum0 += __shfl_xor_sync(0xffffffffu, sum0, 2);
    sum1 += __shfl_xor_sync(0xffffffffu, sum1, 1);
    sum1 += __shfl_xor_sync(0xffffffffu, sum1, 2);
    l0 = l0 * cr0 + sum0;
    l1 = l1 * cr1 + sum1;

#pragma unroll
    for (int nd = 0; nd < 8; nd++) {
      o[nd][0] *= cr0; o[nd][1] *= cr0;
      o[nd][2] *= cr1; o[nd][3] *= cr1;
    }

    // O += P @ V. P fragments come straight from sa (C frag == A frag).
#pragma unroll
    for (int kp = 0; kp < 4; kp++) {
      unsigned pa0, pa1, pa2, pa3;
      F22H(pa0, sa[2 * kp][0], sa[2 * kp][1]);
      F22H(pa1, sa[2 * kp][2], sa[2 * kp][3]);
      F22H(pa2, sa[2 * kp + 1][0], sa[2 * kp + 1][1]);
      F22H(pa3, sa[2 * kp + 1][2], sa[2 * kp + 1][3]);
#pragma unroll
      for (int nd = 0; nd < 8; nd++) {
        const int dc = nd * 8 + lq;          // d column
        unsigned b0 = smu[vsb + dc * 36 + kp * 8 + lt];
        unsigned b1 = smu[vsb + dc * 36 + kp * 8 + lt + 4];
        MMA_F16(o[nd][0], o[nd][1], o[nd][2], o[nd][3],
                pa0, pa1, pa2, pa3, b0, b1);
      }
    }

    if (it + 1 < Sn / 64) ATT_STORE(AT_KV0 + ((it + 1) & 1) * 4608)
    __syncthreads();
  }

  // Final write: rows rw+lq, rw+lq+8; cols nd*8 + 2*lt (half2)
  const float i0 = 1.0f / l0;
  const float i1 = 1.0f / l1;
  const size_t row0 = (size_t)(b * Sn + sQ + rw + lq) * Dn + h * HDn;
  const size_t row1 = (size_t)(b * Sn + sQ + rw + lq + 8) * Dn + h * HDn;
#pragma unroll
  for (int nd = 0; nd < 8; nd++) {
    const int c = nd * 8 + lt * 2;
    unsigned u0, u1;
    F22H(u0, o[nd][0] * i0, o[nd][1] * i0);
    F22H(u1, o[nd][2] * i1, o[nd][3] * i1);
    *(unsigned*)&g_ctxh[row0 + c] = u0;
    *(unsigned*)&g_ctxh[row1 + c] = u1;
  }
}

// ---------------------------------------------------------------------------
// Residual + LayerNorm (fp32, unchanged)
// ---------------------------------------------------------------------------
__device__ __forceinline__ float block_sum(float v, float* red) {
#pragma unroll
  for (int o = 16; o; o >>= 1) v += __shfl_xor_sync(0xffffffffu, v, o);
  if ((threadIdx.x & 31) == 0) red[threadIdx.x >> 5] = v;
  __syncthreads();
  float tot = red[0] + red[1] + red[2] + red[3] +
              red[4] + red[5] + red[6] + red[7];
  __syncthreads();
  return tot;
}

__global__ __launch_bounds__(256) void ln_kernel(
    const float* __restrict__ x, const float* __restrict__ gamma,
    const float* __restrict__ beta, float* __restrict__ out) {
  __shared__ float red[8];
  const int row = blockIdx.x;
  const int c   = threadIdx.x * 4;

  float4 y  = *(const float4*)&g_proj[(size_t)row * Dn + c];
  float4 xv = *(const float4*)&x[(size_t)row * Dn + c];
  y.x += xv.x; y.y += xv.y; y.z += xv.z; y.w += xv.w;

  float tot = block_sum(y.x + y.y + y.z + y.w, red);
  const float mu = tot * (1.0f / Dn);

  float dx = y.x - mu, dy = y.y - mu, dz = y.z - mu, dw = y.w - mu;
  float sq = block_sum(dx * dx + dy * dy + dz * dz + dw * dw, red);
  const float var = sq * (1.0f / Dn);
  const float r = rsqrtf(var + 1e-5f);

  float4 g  = *(const float4*)&gamma[c];
  float4 bt = *(const float4*)&beta[c];
  float4 o;
  o.x = dx * r * g.x + bt.x;
  o.y = dy * r * g.y + bt.y;
  o.z = dz * r * g.z + bt.z;
  o.w = dw * r * g.w + bt.w;
  *(float4*)&out[(size_t)row * Dn + c] = o;
}

// ---------------------------------------------------------------------------
// Launch — only harness-provided pointers cross the host/device boundary.
// ---------------------------------------------------------------------------
extern "C" void kernel_launch(void* const* d_in, const int* in_sizes, int n_in,
                              void* d_out, int out_size) {
  (void)in_sizes; (void)n_in; (void)out_size;
  const float* x     = (const float*)d_in[0];
  const float* W_qkv = (const float*)d_in[1];
  const float* b_qkv = (const float*)d_in[2];
  const float* W_out = (const float*)d_in[3];
  const float* b_out = (const float*)d_in[4];
  const float* gamma = (const float*)d_in[5];
  const float* beta  = (const float*)d_in[6];
  float* out = (float*)d_out;

  const int attn_smem = ATTN_SMEM_WORDS * 4;  // 55296 B
  cudaFuncSetAttribute(attn_f16_kernel,
                       cudaFuncAttributeMaxDynamicSharedMemorySize, attn_smem);

  gemm_f16_kernel<N3, 1><<<dim3(N3 / 128, (Bn * Sn) / 128), 256>>>(
      x, W_qkv, b_qkv);
  attn_f16_kernel<<<dim3(Sn / 128, Hn, Bn), 256, attn_smem>>>();
  gemm_f16_kernel<Dn, 0><<<dim3(Dn / 128, (Bn * Sn) / 128), 256>>>(
      x, W_out, b_out);
  ln_kernel<<<Bn * Sn, 256>>>(x, gamma, beta, out);
}

// round 8
// speedup vs baseline: 5.4413x; 1.2256x over previous
#include <cuda_runtime.h>
#include <cuda_fp16.h>
#include <math.h>

// Problem constants
#define Bn 4
#define Sn 2048
#define Dn 1024
#define Hn 16
#define HDn 64
#define N3 3072   // 3*Dn

// ---------------------------------------------------------------------------
// Device scratch (referenced ONLY in device code — R5 ATS lesson)
// ---------------------------------------------------------------------------
__device__ __half   g_xh[(size_t)Bn * Sn * Dn];         // x as half
__device__ unsigned g_wqkvp[(size_t)512 * N3];          // W_qkv k-pair packed
__device__ unsigned g_woutp[(size_t)512 * Dn];          // W_out k-pair packed
__device__ __half   g_qh[(size_t)Bn * Hn * Sn * HDn];   // pre-scaled by 1/8
__device__ __half   g_kh[(size_t)Bn * Hn * Sn * HDn];
__device__ __half   g_vh[(size_t)Bn * Hn * HDn * Sn];   // [Hd][S] transposed
__device__ __half   g_ctxh[(size_t)Bn * Sn * Dn];
__device__ float    g_proj[(size_t)Bn * Sn * Dn];

// Pack two floats -> f16x2 (lo = first elem, hi = second).
#define F22H(u, lo, hi)                                                      \
  asm("cvt.rn.f16x2.f32 %0, %1, %2;" : "=r"(u) : "f"(hi), "f"(lo))

// fp16 mma, fp32 accumulate; macro binds operands to lvalues (no lmem).
#define MMA_F16(c0, c1, c2, c3, a0, a1, a2, a3, b0, b1)                      \
  asm volatile(                                                              \
      "mma.sync.aligned.m16n8k16.row.col.f32.f16.f16.f32 "                   \
      "{%0,%1,%2,%3},{%4,%5,%6,%7},{%8,%9},{%0,%1,%2,%3};"                   \
      : "+f"(c0), "+f"(c1), "+f"(c2), "+f"(c3)                               \
      : "r"(a0), "r"(a1), "r"(a2), "r"(a3), "r"(b0), "r"(b1))

// ---------------------------------------------------------------------------
// Conversion kernels (run once per launch; deterministic)
// ---------------------------------------------------------------------------
__global__ __launch_bounds__(256) void cvt_x_kernel(const float* __restrict__ x) {
  const size_t i = ((size_t)blockIdx.x * 256 + threadIdx.x) * 4;
  float4 v = *(const float4*)&x[i];
  unsigned u0, u1;
  F22H(u0, v.x, v.y);
  F22H(u1, v.z, v.w);
  *(uint2*)&g_xh[i] = make_uint2(u0, u1);
}

// word[kp][n] = pack(W[2kp][n], W[2kp+1][n]);  WHICH: 1 = qkv, 0 = out
template <int NDIM, int WHICH>
__global__ __launch_bounds__(256) void cvt_w_kernel(const float* __restrict__ W) {
  const int idx = blockIdx.x * 256 + threadIdx.x;   // word index
  const int kp  = idx / NDIM;
  const int n   = idx - kp * NDIM;
  unsigned u;
  F22H(u, W[(size_t)(2 * kp) * NDIM + n], W[(size_t)(2 * kp + 1) * NDIM + n]);
  if (WHICH)
    g_wqkvp[idx] = u;
  else
    g_woutp[idx] = u;
}

// ---------------------------------------------------------------------------
// QKV scatter epilogue helper (half outputs; Q pre-scaled by 0.125)
// ---------------------------------------------------------------------------
__device__ __forceinline__ void scatter_qkv(int m, int n, float val) {
  const int sec = n >> 10;            // 0=Q,1=K,2=V
  const int h   = (n & 1023) >> 6;
  const int hd  = n & 63;
  const int b   = m >> 11;
  const int s   = m & 2047;
  if (sec == 0)
    g_qh[((size_t)(b * Hn + h) * Sn + s) * HDn + hd] =
        __float2half_rn(val * 0.125f);
  else if (sec == 1)
    g_kh[((size_t)(b * Hn + h) * Sn + s) * HDn + hd] = __float2half_rn(val);
  else
    g_vh[((size_t)(b * Hn + h) * HDn + hd) * Sn + s] = __float2half_rn(val);
}

// ---------------------------------------------------------------------------
// FP16 GEMM: C[8192, NDIM] = Asrc @ W + bias. All operands half in gmem.
// Block 128x128, BK=32, 256 threads, 8 warps (4x2), warp tile 32x64.
// Double-buffered smem, raw uint4 copies (no cvt in hot loop).
// MODE 1: Asrc=g_xh, B=g_wqkvp, QKV scatter. MODE 0: Asrc=g_ctxh, B=g_woutp,
// write g_proj.
// ---------------------------------------------------------------------------
#define G_LOAD_A(kk)                                                         \
  { int idx = t;       int row = idx >> 2, c16 = idx & 3;                    \
    ha0 = *(const uint4*)&Ah[(size_t)(m0 + row) * Dn + (kk) + c16 * 8]; }    \
  { int idx = t + 256; int row = idx >> 2, c16 = idx & 3;                    \
    ha1 = *(const uint4*)&Ah[(size_t)(m0 + row) * Dn + (kk) + c16 * 8]; }

#define G_LOAD_B(kk)                                                         \
  { int idx = t;       int kp = idx >> 5, n4 = (idx & 31) * 4;               \
    hb0 = *(const uint4*)&Wp[(size_t)((kk) / 2 + kp) * NDIM + n0 + n4]; }    \
  { int idx = t + 256; int kp = idx >> 5, n4 = (idx & 31) * 4;               \
    hb1 = *(const uint4*)&Wp[(size_t)((kk) / 2 + kp) * NDIM + n0 + n4]; }

#define G_STORE_A(bb)                                                        \
  { int idx = t;       int row = idx >> 2, c16 = idx & 3;                    \
    *(uint4*)&As2[bb][row][c16 * 4] = ha0; }                                 \
  { int idx = t + 256; int row = idx >> 2, c16 = idx & 3;                    \
    *(uint4*)&As2[bb][row][c16 * 4] = ha1; }

#define G_STORE_B(bb)                                                        \
  { int idx = t;       int kp = idx >> 5, n4 = (idx & 31) * 4;               \
    *(uint4*)&Bs2[bb][kp][n4] = hb0; }                                       \
  { int idx = t + 256; int kp = idx >> 5, n4 = (idx & 31) * 4;               \
    *(uint4*)&Bs2[bb][kp][n4] = hb1; }

template <int NDIM, int MODE>
__global__ __launch_bounds__(256) void gemm_f16_kernel(
    const float* __restrict__ bias) {
  __shared__ __align__(16) unsigned As2[2][128][20];
  __shared__ __align__(16) unsigned Bs2[2][16][136];

  const __half*   __restrict__ Ah = (MODE == 1) ? g_xh : g_ctxh;
  const unsigned* __restrict__ Wp = (MODE == 1) ? g_wqkvp : g_woutp;

  const int t    = threadIdx.x;
  const int lane = t & 31;
  const int lq   = lane >> 2;
  const int lt   = lane & 3;
  const int warp = t >> 5;
  const int wm   = warp >> 1;
  const int wn   = warp & 1;
  const int n0   = blockIdx.x * 128;
  const int m0   = blockIdx.y * 128;

  uint4 ha0, ha1, hb0, hb1;

  float acc[2][8][4];
#pragma unroll
  for (int mt = 0; mt < 2; mt++)
#pragma unroll
    for (int nt = 0; nt < 8; nt++)
#pragma unroll
      for (int j = 0; j < 4; j++) acc[mt][nt][j] = 0.0f;

  G_LOAD_A(0)
  G_LOAD_B(0)
  G_STORE_A(0)
  G_STORE_B(0)
  __syncthreads();

  for (int it = 0; it < Dn / 32; it++) {
    const int bb = it & 1;
    if (it + 1 < Dn / 32) {
      const int kn = (it + 1) * 32;
      G_LOAD_A(kn)
      G_LOAD_B(kn)
    }

#pragma unroll
    for (int ks = 0; ks < 2; ks++) {
      const int pb = ks * 8;
      unsigned a00, a01, a02, a03, a10, a11, a12, a13;
      {
        const int r = wm * 32 + lq;
        a00 = As2[bb][r][pb + lt];
        a01 = As2[bb][r + 8][pb + lt];
        a02 = As2[bb][r][pb + lt + 4];
        a03 = As2[bb][r + 8][pb + lt + 4];
        a10 = As2[bb][r + 16][pb + lt];
        a11 = As2[bb][r + 24][pb + lt];
        a12 = As2[bb][r + 16][pb + lt + 4];
        a13 = As2[bb][r + 24][pb + lt + 4];
      }
#pragma unroll
      for (int nt = 0; nt < 8; nt++) {
        const int n  = wn * 64 + nt * 8 + lq;
        unsigned b0 = Bs2[bb][pb + lt][n];
        unsigned b1 = Bs2[bb][pb + lt + 4][n];
        MMA_F16(acc[0][nt][0], acc[0][nt][1], acc[0][nt][2], acc[0][nt][3],
                a00, a01, a02, a03, b0, b1);
        MMA_F16(acc[1][nt][0], acc[1][nt][1], acc[1][nt][2], acc[1][nt][3],
                a10, a11, a12, a13, b0, b1);
      }
    }
    if (it + 1 < Dn / 32) {
      G_STORE_A(1 - bb)
      G_STORE_B(1 - bb)
    }
    __syncthreads();
  }

  // Epilogue
#pragma unroll
  for (int mt = 0; mt < 2; mt++) {
    const int r0 = m0 + wm * 32 + mt * 16 + lq;
#pragma unroll
    for (int nt = 0; nt < 8; nt++) {
      const int c0 = n0 + wn * 64 + nt * 8 + lt * 2;
      float v0 = acc[mt][nt][0] + bias[c0];
      float v1 = acc[mt][nt][1] + bias[c0 + 1];
      float v2 = acc[mt][nt][2] + bias[c0];
      float v3 = acc[mt][nt][3] + bias[c0 + 1];
      if (MODE == 0) {
        g_proj[(size_t)r0 * Dn + c0]           = v0;
        g_proj[(size_t)r0 * Dn + c0 + 1]       = v1;
        g_proj[(size_t)(r0 + 8) * Dn + c0]     = v2;
        g_proj[(size_t)(r0 + 8) * Dn + c0 + 1] = v3;
      } else {
        scatter_qkv(r0, c0, v0);
        scatter_qkv(r0, c0 + 1, v1);
        scatter_qkv(r0 + 8, c0, v2);
        scatter_qkv(r0 + 8, c0 + 1, v3);
      }
    }
  }
}

// ---------------------------------------------------------------------------
// Flash attention, FA2-style: 8 warps x 16-row stripes, register softmax,
// K/V double-buffered, Q FRAGMENTS HOISTED to registers (tile-invariant).
// Smem words: Qs 4608 + KV 2x4608 = 13824 (55 KB). 1 sync per key tile.
// ---------------------------------------------------------------------------
#define AT_KV0 4608
#define ATTN_SMEM_WORDS 13824

#define ATT_LOAD(kk)                                                         \
  { int idx = t;       int row = idx >> 3, c16 = idx & 7;                    \
    kr0 = *(const uint4*)&g_kh[baseQK + (size_t)((kk) + row) * HDn + c16*8]; \
    vr0 = *(const uint4*)&g_vh[baseV + (size_t)row * Sn + (kk) + c16 * 8]; } \
  { int idx = t + 256; int row = idx >> 3, c16 = idx & 7;                    \
    kr1 = *(const uint4*)&g_kh[baseQK + (size_t)((kk) + row) * HDn + c16*8]; \
    vr1 = *(const uint4*)&g_vh[baseV + (size_t)row * Sn + (kk) + c16 * 8]; }

#define ATT_STORE(base)                                                      \
  { int idx = t;       int row = idx >> 3, c16 = idx & 7;                    \
    *(uint4*)&smu[(base) + row * 36 + c16 * 4]        = kr0;                 \
    *(uint4*)&smu[(base) + 2304 + row * 36 + c16 * 4] = vr0; }               \
  { int idx = t + 256; int row = idx >> 3, c16 = idx & 7;                    \
    *(uint4*)&smu[(base) + row * 36 + c16 * 4]        = kr1;                 \
    *(uint4*)&smu[(base) + 2304 + row * 36 + c16 * 4] = vr1; }

__global__ __launch_bounds__(256) void attn_f16_kernel() {
  extern __shared__ __align__(16) unsigned smu[];

  const int t    = threadIdx.x;
  const int lane = t & 31;
  const int lq   = lane >> 2;
  const int lt   = lane & 3;
  const int warp = t >> 5;
  const int rw   = warp * 16;
  const int b    = blockIdx.z;
  const int h    = blockIdx.y;
  const int sQ   = blockIdx.x * 128;

  const size_t baseQK = (size_t)(b * Hn + h) * Sn * HDn;
  const size_t baseV  = (size_t)(b * Hn + h) * HDn * Sn;

  uint4 kr0, kr1, vr0, vr1;

  // Q tile (pre-scaled): copies into pair-interleaved [q][dpair] stride 36
#pragma unroll
  for (int i = 0; i < 4; i++) {
    int idx = t + i * 256;
    int row = idx >> 3, c16 = idx & 7;
    *(uint4*)&smu[row * 36 + c16 * 4] =
        *(const uint4*)&g_qh[baseQK + (size_t)(sQ + row) * HDn + c16 * 8];
  }

  ATT_LOAD(0)
  ATT_STORE(AT_KV0)
  __syncthreads();

  // Hoist Q A-fragments (invariant across key tiles): 16 regs.
  unsigned qa0[4], qa1[4], qa2[4], qa3[4];
#pragma unroll
  for (int ks = 0; ks < 4; ks++) {
    const int r = rw + lq;
    qa0[ks] = smu[r * 36 + ks * 8 + lt];
    qa1[ks] = smu[(r + 8) * 36 + ks * 8 + lt];
    qa2[ks] = smu[r * 36 + ks * 8 + lt + 4];
    qa3[ks] = smu[(r + 8) * 36 + ks * 8 + lt + 4];
  }

  float m0 = -INFINITY, m1 = -INFINITY, l0 = 0.0f, l1 = 0.0f;
  float o[8][4];
#pragma unroll
  for (int nd = 0; nd < 8; nd++)
#pragma unroll
    for (int j = 0; j < 4; j++) o[nd][j] = 0.0f;

  for (int it = 0; it < Sn / 64; it++) {
    const int ksb = AT_KV0 + (it & 1) * 4608;
    const int vsb = ksb + 2304;
    if (it + 1 < Sn / 64) ATT_LOAD((it + 1) * 64)

    // S = Q K^T : warp computes 16x64
    float sa[8][4];
#pragma unroll
    for (int nt = 0; nt < 8; nt++)
#pragma unroll
      for (int j = 0; j < 4; j++) sa[nt][j] = 0.0f;

#pragma unroll
    for (int ks = 0; ks < 4; ks++) {
#pragma unroll
      for (int nt = 0; nt < 8; nt++) {
        const int kc = nt * 8 + lq;
        unsigned b0 = smu[ksb + kc * 36 + ks * 8 + lt];
        unsigned b1 = smu[ksb + kc * 36 + ks * 8 + lt + 4];
        MMA_F16(sa[nt][0], sa[nt][1], sa[nt][2], sa[nt][3],
                qa0[ks], qa1[ks], qa2[ks], qa3[ks], b0, b1);
      }
    }

    // Register softmax (row in 4 lt lanes)
    float mx0 = -INFINITY, mx1 = -INFINITY;
#pragma unroll
    for (int nt = 0; nt < 8; nt++) {
      mx0 = fmaxf(mx0, fmaxf(sa[nt][0], sa[nt][1]));
      mx1 = fmaxf(mx1, fmaxf(sa[nt][2], sa[nt][3]));
    }
    mx0 = fmaxf(mx0, __shfl_xor_sync(0xffffffffu, mx0, 1));
    mx0 = fmaxf(mx0, __shfl_xor_sync(0xffffffffu, mx0, 2));
    mx1 = fmaxf(mx1, __shfl_xor_sync(0xffffffffu, mx1, 1));
    mx1 = fmaxf(mx1, __shfl_xor_sync(0xffffffffu, mx1, 2));
    const float mn0 = fmaxf(m0, mx0);
    const float mn1 = fmaxf(m1, mx1);
    const float cr0 = __expf(m0 - mn0);
    const float cr1 = __expf(m1 - mn1);
    m0 = mn0; m1 = mn1;

    float sum0 = 0.0f, sum1 = 0.0f;
#pragma unroll
    for (int nt = 0; nt < 8; nt++) {
      sa[nt][0] = __expf(sa[nt][0] - mn0);
      sa[nt][1] = __expf(sa[nt][1] - mn0);
      sa[nt][2] = __expf(sa[nt][2] - mn1);
      sa[nt][3] = __expf(sa[nt][3] - mn1);
      sum0 += sa[nt][0] + sa[nt][1];
      sum1 += sa[nt][2] + sa[nt][3];
    }
    sum0 += __shfl_xor_sync(0xffffffffu, sum0, 1);
    sum0 += __shfl_xor_sync(0xffffffffu, sum0, 2);
    sum1 += __shfl_xor_sync(0xffffffffu, sum1, 1);
    sum1 += __shfl_xor_sync(0xffffffffu, sum1, 2);
    l0 = l0 * cr0 + sum0;
    l1 = l1 * cr1 + sum1;

#pragma unroll
    for (int nd = 0; nd < 8; nd++) {
      o[nd][0] *= cr0; o[nd][1] *= cr0;
      o[nd][2] *= cr1; o[nd][3] *= cr1;
    }

    // O += P @ V  (C frag == A frag)
#pragma unroll
    for (int kp = 0; kp < 4; kp++) {
      unsigned pa0, pa1, pa2, pa3;
      F22H(pa0, sa[2 * kp][0], sa[2 * kp][1]);
      F22H(pa1, sa[2 * kp][2], sa[2 * kp][3]);
      F22H(pa2, sa[2 * kp + 1][0], sa[2 * kp + 1][1]);
      F22H(pa3, sa[2 * kp + 1][2], sa[2 * kp + 1][3]);
#pragma unroll
      for (int nd = 0; nd < 8; nd++) {
        const int dc = nd * 8 + lq;
        unsigned b0 = smu[vsb + dc * 36 + kp * 8 + lt];
        unsigned b1 = smu[vsb + dc * 36 + kp * 8 + lt + 4];
        MMA_F16(o[nd][0], o[nd][1], o[nd][2], o[nd][3],
                pa0, pa1, pa2, pa3, b0, b1);
      }
    }

    if (it + 1 < Sn / 64) ATT_STORE(AT_KV0 + ((it + 1) & 1) * 4608)
    __syncthreads();
  }

  const float i0 = 1.0f / l0;
  const float i1 = 1.0f / l1;
  const size_t row0 = (size_t)(b * Sn + sQ + rw + lq) * Dn + h * HDn;
  const size_t row1 = (size_t)(b * Sn + sQ + rw + lq + 8) * Dn + h * HDn;
#pragma unroll
  for (int nd = 0; nd < 8; nd++) {
    const int c = nd * 8 + lt * 2;
    unsigned u0, u1;
    F22H(u0, o[nd][0] * i0, o[nd][1] * i0);
    F22H(u1, o[nd][2] * i1, o[nd][3] * i1);
    *(unsigned*)&g_ctxh[row0 + c] = u0;
    *(unsigned*)&g_ctxh[row1 + c] = u1;
  }
}

// ---------------------------------------------------------------------------
// Residual + LayerNorm (fp32, unchanged)
// ---------------------------------------------------------------------------
__device__ __forceinline__ float block_sum(float v, float* red) {
#pragma unroll
  for (int o = 16; o; o >>= 1) v += __shfl_xor_sync(0xffffffffu, v, o);
  if ((threadIdx.x & 31) == 0) red[threadIdx.x >> 5] = v;
  __syncthreads();
  float tot = red[0] + red[1] + red[2] + red[3] +
              red[4] + red[5] + red[6] + red[7];
  __syncthreads();
  return tot;
}

__global__ __launch_bounds__(256) void ln_kernel(
    const float* __restrict__ x, const float* __restrict__ gamma,
    const float* __restrict__ beta, float* __restrict__ out) {
  __shared__ float red[8];
  const int row = blockIdx.x;
  const int c   = threadIdx.x * 4;

  float4 y  = *(const float4*)&g_proj[(size_t)row * Dn + c];
  float4 xv = *(const float4*)&x[(size_t)row * Dn + c];
  y.x += xv.x; y.y += xv.y; y.z += xv.z; y.w += xv.w;

  float tot = block_sum(y.x + y.y + y.z + y.w, red);
  const float mu = tot * (1.0f / Dn);

  float dx = y.x - mu, dy = y.y - mu, dz = y.z - mu, dw = y.w - mu;
  float sq = block_sum(dx * dx + dy * dy + dz * dz + dw * dw, red);
  const float var = sq * (1.0f / Dn);
  const float r = rsqrtf(var + 1e-5f);

  float4 g  = *(const float4*)&gamma[c];
  float4 bt = *(const float4*)&beta[c];
  float4 o;
  o.x = dx * r * g.x + bt.x;
  o.y = dy * r * g.y + bt.y;
  o.z = dz * r * g.z + bt.z;
  o.w = dw * r * g.w + bt.w;
  *(float4*)&out[(size_t)row * Dn + c] = o;
}

// ---------------------------------------------------------------------------
// Launch — only harness pointers cross the host/device boundary.
// ---------------------------------------------------------------------------
extern "C" void kernel_launch(void* const* d_in, const int* in_sizes, int n_in,
                              void* d_out, int out_size) {
  (void)in_sizes; (void)n_in; (void)out_size;
  const float* x     = (const float*)d_in[0];
  const float* W_qkv = (const float*)d_in[1];
  const float* b_qkv = (const float*)d_in[2];
  const float* W_out = (const float*)d_in[3];
  const float* b_out = (const float*)d_in[4];
  const float* gamma = (const float*)d_in[5];
  const float* beta  = (const float*)d_in[6];
  float* out = (float*)d_out;

  const int attn_smem = ATTN_SMEM_WORDS * 4;  // 55296 B
  cudaFuncSetAttribute(attn_f16_kernel,
                       cudaFuncAttributeMaxDynamicSharedMemorySize, attn_smem);

  cvt_x_kernel<<<(Bn * Sn * Dn) / 1024, 256>>>(x);
  cvt_w_kernel<N3, 1><<<2 * N3, 256>>>(W_qkv);
  cvt_w_kernel<Dn, 0><<<2 * Dn, 256>>>(W_out);

  gemm_f16_kernel<N3, 1><<<dim3(N3 / 128, (Bn * Sn) / 128), 256>>>(b_qkv);
  attn_f16_kernel<<<dim3(Sn / 128, Hn, Bn), 256, attn_smem>>>();
  gemm_f16_kernel<Dn, 0><<<dim3(Dn / 128, (Bn * Sn) / 128), 256>>>(b_out);
  ln_kernel<<<Bn * Sn, 256>>>(x, gamma, beta, out);
}

// round 9
// speedup vs baseline: 5.9941x; 1.1016x over previous
#include <cuda_runtime.h>
#include <cuda_fp16.h>
#include <math.h>

// Problem constants
#define Bn 4
#define Sn 2048
#define Dn 1024
#define Hn 16
#define HDn 64
#define N3 3072   // 3*Dn

// ---------------------------------------------------------------------------
// Device scratch (referenced ONLY in device code — R5 ATS lesson)
// ---------------------------------------------------------------------------
__device__ __half g_xh[(size_t)Bn * Sn * Dn];        // x as half [m][k]
__device__ __half g_wqkvh[(size_t)Dn * N3];          // W_qkv half [k][n]
__device__ __half g_wouth[(size_t)Dn * Dn];          // W_out half [k][n]
__device__ __half g_qh[(size_t)Bn * Hn * Sn * HDn];  // pre-scaled by 1/8
__device__ __half g_kh[(size_t)Bn * Hn * Sn * HDn];
__device__ __half g_vh[(size_t)Bn * Hn * HDn * Sn];  // [Hd][S] transposed
__device__ __half g_ctxh[(size_t)Bn * Sn * Dn];
__device__ float  g_proj[(size_t)Bn * Sn * Dn];

// Pack two floats -> f16x2 (lo = first elem, hi = second).
#define F22H(u, lo, hi)                                                      \
  asm("cvt.rn.f16x2.f32 %0, %1, %2;" : "=r"(u) : "f"(hi), "f"(lo))

// fp16 mma, fp32 accumulate; macro binds operands to lvalues (no lmem).
#define MMA_F16(c0, c1, c2, c3, a0, a1, a2, a3, b0, b1)                      \
  asm volatile(                                                              \
      "mma.sync.aligned.m16n8k16.row.col.f32.f16.f16.f32 "                   \
      "{%0,%1,%2,%3},{%4,%5,%6,%7},{%8,%9},{%0,%1,%2,%3};"                   \
      : "+f"(c0), "+f"(c1), "+f"(c2), "+f"(c3)                               \
      : "r"(a0), "r"(a1), "r"(a2), "r"(a3), "r"(b0), "r"(b1))

// ldmatrix x4: 4 fragments per instruction.
#define LDSM4(d0, d1, d2, d3, a)                                             \
  asm volatile(                                                              \
      "ldmatrix.sync.aligned.m8n8.x4.shared.b16 {%0,%1,%2,%3},[%4];"         \
      : "=r"(d0), "=r"(d1), "=r"(d2), "=r"(d3) : "r"(a))
#define LDSM4T(d0, d1, d2, d3, a)                                            \
  asm volatile(                                                              \
      "ldmatrix.sync.aligned.m8n8.x4.trans.shared.b16 {%0,%1,%2,%3},[%4];"   \
      : "=r"(d0), "=r"(d1), "=r"(d2), "=r"(d3) : "r"(a))

#define SMEM_U32(p) ((unsigned)__cvta_generic_to_shared(p))

// ---------------------------------------------------------------------------
// Conversion kernels (once per launch; deterministic)
// ---------------------------------------------------------------------------
__global__ __launch_bounds__(256) void cvt_x_kernel(const float* __restrict__ x) {
  const size_t i = ((size_t)blockIdx.x * 256 + threadIdx.x) * 4;
  float4 v = *(const float4*)&x[i];
  unsigned u0, u1;
  F22H(u0, v.x, v.y);
  F22H(u1, v.z, v.w);
  *(uint2*)&g_xh[i] = make_uint2(u0, u1);
}

template <int WHICH>   // 1 = qkv, 0 = out
__global__ __launch_bounds__(256) void cvt_w_kernel(const float* __restrict__ W) {
  const size_t i = ((size_t)blockIdx.x * 256 + threadIdx.x) * 4;
  float4 v = *(const float4*)&W[i];
  unsigned u0, u1;
  F22H(u0, v.x, v.y);
  F22H(u1, v.z, v.w);
  __half* dst = WHICH ? g_wqkvh : g_wouth;
  *(uint2*)&dst[i] = make_uint2(u0, u1);
}

// ---------------------------------------------------------------------------
// QKV scatter epilogue helper (half outputs; Q pre-scaled by 0.125)
// ---------------------------------------------------------------------------
__device__ __forceinline__ void scatter_qkv(int m, int n, float val) {
  const int sec = n >> 10;
  const int h   = (n & 1023) >> 6;
  const int hd  = n & 63;
  const int b   = m >> 11;
  const int s   = m & 2047;
  if (sec == 0)
    g_qh[((size_t)(b * Hn + h) * Sn + s) * HDn + hd] =
        __float2half_rn(val * 0.125f);
  else if (sec == 1)
    g_kh[((size_t)(b * Hn + h) * Sn + s) * HDn + hd] = __float2half_rn(val);
  else
    g_vh[((size_t)(b * Hn + h) * HDn + hd) * Sn + s] = __float2half_rn(val);
}

// ---------------------------------------------------------------------------
// FP16 GEMM: block 128x128, BK=32, 8 warps (4x2), warp tile 32x64.
// Double-buffered smem; ldmatrix fragment loads.
// Ash [m][40 halfs] (stride 80B: 16B-aligned, LDSM conflict-free)
// Bsh [k][136 halfs] (stride 272B: aligned, conflict-free)
// ---------------------------------------------------------------------------
#define G_LOAD_A(kk)                                                         \
  { int idx = t;       int row = idx >> 2, c = (idx & 3) * 8;                \
    ha0 = *(const uint4*)&Ah[(size_t)(m0 + row) * Dn + (kk) + c]; }          \
  { int idx = t + 256; int row = idx >> 2, c = (idx & 3) * 8;                \
    ha1 = *(const uint4*)&Ah[(size_t)(m0 + row) * Dn + (kk) + c]; }

#define G_LOAD_B(kk)                                                         \
  { int idx = t;       int row = idx >> 4, c = (idx & 15) * 8;               \
    hb0 = *(const uint4*)&Wh[(size_t)((kk) + row) * NDIM + n0 + c]; }        \
  { int idx = t + 256; int row = idx >> 4, c = (idx & 15) * 8;               \
    hb1 = *(const uint4*)&Wh[(size_t)((kk) + row) * NDIM + n0 + c]; }

#define G_STORE_A(bb)                                                        \
  { int idx = t;       int row = idx >> 2, c = (idx & 3) * 8;                \
    *(uint4*)&Ash[bb][row][c] = ha0; }                                       \
  { int idx = t + 256; int row = idx >> 2, c = (idx & 3) * 8;                \
    *(uint4*)&Ash[bb][row][c] = ha1; }

#define G_STORE_B(bb)                                                        \
  { int idx = t;       int row = idx >> 4, c = (idx & 15) * 8;               \
    *(uint4*)&Bsh[bb][row][c] = hb0; }                                       \
  { int idx = t + 256; int row = idx >> 4, c = (idx & 15) * 8;               \
    *(uint4*)&Bsh[bb][row][c] = hb1; }

template <int NDIM, int MODE>
__global__ __launch_bounds__(256) void gemm_f16_kernel(
    const float* __restrict__ bias) {
  __shared__ __align__(16) __half Ash[2][128][40];
  __shared__ __align__(16) __half Bsh[2][32][136];

  const __half* __restrict__ Ah = (MODE == 1) ? g_xh : g_ctxh;
  const __half* __restrict__ Wh = (MODE == 1) ? g_wqkvh : g_wouth;

  const int t    = threadIdx.x;
  const int lane = t & 31;
  const int lq   = lane >> 2;
  const int lt   = lane & 3;
  const int warp = t >> 5;
  const int wm   = warp >> 1;
  const int wn   = warp & 1;
  const int n0   = blockIdx.x * 128;
  const int m0   = blockIdx.y * 128;

  // ldmatrix lane-address components (constant over loop)
  const int l8  = lane & 7;
  const int mhi = (lane >> 3) & 1;   // matrix-pair selector
  const int mvh = (lane >> 4) & 1;

  uint4 ha0, ha1, hb0, hb1;

  float acc[2][8][4];
#pragma unroll
  for (int mt = 0; mt < 2; mt++)
#pragma unroll
    for (int nt = 0; nt < 8; nt++)
#pragma unroll
      for (int j = 0; j < 4; j++) acc[mt][nt][j] = 0.0f;

  G_LOAD_A(0)
  G_LOAD_B(0)
  G_STORE_A(0)
  G_STORE_B(0)
  __syncthreads();

  for (int it = 0; it < Dn / 32; it++) {
    const int bb = it & 1;
    if (it + 1 < Dn / 32) {
      const int kn = (it + 1) * 32;
      G_LOAD_A(kn)
      G_LOAD_B(kn)
    }

#pragma unroll
    for (int ks = 0; ks < 2; ks++) {
      const int kb = ks * 16;
      // A fragments: m0=(r,kb) m1=(r+8,kb) m2=(r,kb+8) m3=(r+8,kb+8)
      unsigned a0[4], a1[4];
      {
        const int rowA = wm * 32 + mhi * 8 + l8;
        const int kA   = kb + mvh * 8;
        LDSM4(a0[0], a0[1], a0[2], a0[3],
              SMEM_U32(&Ash[bb][rowA][kA]));
        LDSM4(a1[0], a1[1], a1[2], a1[3],
              SMEM_U32(&Ash[bb][rowA + 16][kA]));
      }
#pragma unroll
      for (int ng = 0; ng < 4; ng++) {
        // B trans: m0=(kb,nb) m1=(kb+8,nb) m2=(kb,nb+8) m3=(kb+8,nb+8)
        const int krow = kb + mhi * 8 + l8;
        const int nB   = wn * 64 + ng * 16 + mvh * 8;
        unsigned b0, b1, b2, b3;
        LDSM4T(b0, b1, b2, b3, SMEM_U32(&Bsh[bb][krow][nB]));
        const int nt0 = ng * 2, nt1 = ng * 2 + 1;
        MMA_F16(acc[0][nt0][0], acc[0][nt0][1], acc[0][nt0][2], acc[0][nt0][3],
                a0[0], a0[1], a0[2], a0[3], b0, b1);
        MMA_F16(acc[1][nt0][0], acc[1][nt0][1], acc[1][nt0][2], acc[1][nt0][3],
                a1[0], a1[1], a1[2], a1[3], b0, b1);
        MMA_F16(acc[0][nt1][0], acc[0][nt1][1], acc[0][nt1][2], acc[0][nt1][3],
                a0[0], a0[1], a0[2], a0[3], b2, b3);
        MMA_F16(acc[1][nt1][0], acc[1][nt1][1], acc[1][nt1][2], acc[1][nt1][3],
                a1[0], a1[1], a1[2], a1[3], b2, b3);
      }
    }
    if (it + 1 < Dn / 32) {
      G_STORE_A(1 - bb)
      G_STORE_B(1 - bb)
    }
    __syncthreads();
  }

  // Epilogue
#pragma unroll
  for (int mt = 0; mt < 2; mt++) {
    const int r0 = m0 + wm * 32 + mt * 16 + lq;
#pragma unroll
    for (int nt = 0; nt < 8; nt++) {
      const int c0 = n0 + wn * 64 + nt * 8 + lt * 2;
      float v0 = acc[mt][nt][0] + bias[c0];
      float v1 = acc[mt][nt][1] + bias[c0 + 1];
      float v2 = acc[mt][nt][2] + bias[c0];
      float v3 = acc[mt][nt][3] + bias[c0 + 1];
      if (MODE == 0) {
        g_proj[(size_t)r0 * Dn + c0]           = v0;
        g_proj[(size_t)r0 * Dn + c0 + 1]       = v1;
        g_proj[(size_t)(r0 + 8) * Dn + c0]     = v2;
        g_proj[(size_t)(r0 + 8) * Dn + c0 + 1] = v3;
      } else {
        scatter_qkv(r0, c0, v0);
        scatter_qkv(r0, c0 + 1, v1);
        scatter_qkv(r0 + 8, c0, v2);
        scatter_qkv(r0 + 8, c0 + 1, v3);
      }
    }
  }
}

// ---------------------------------------------------------------------------
// Flash attention (FA2): 8 warps x 16-row stripes, register softmax, K/V
// double-buffered, Q fragments hoisted, ALL fragment loads via ldmatrix.
// Smem (halfs, row stride 88 = 176B, aligned + LDSM conflict-free):
//   Q [128][88] = 11264; per KV stage: K [64][88] + V [64][88] = 11264.
//   Total 33792 halfs = 67584 B.
// ---------------------------------------------------------------------------
#define AT_KV0 11264
#define AT_STG 11264
#define ATTN_SMEM_BYTES (33792 * 2)

#define ATT_LOAD(kk)                                                         \
  { int idx = t;       int row = idx >> 3, c = (idx & 7) * 8;                \
    kr0 = *(const uint4*)&g_kh[baseQK + (size_t)((kk) + row) * HDn + c];     \
    vr0 = *(const uint4*)&g_vh[baseV + (size_t)row * Sn + (kk) + c]; }       \
  { int idx = t + 256; int row = idx >> 3, c = (idx & 7) * 8;                \
    kr1 = *(const uint4*)&g_kh[baseQK + (size_t)((kk) + row) * HDn + c];     \
    vr1 = *(const uint4*)&g_vh[baseV + (size_t)row * Sn + (kk) + c]; }

#define ATT_STORE(base)                                                      \
  { int idx = t;       int row = idx >> 3, c = (idx & 7) * 8;                \
    *(uint4*)&smh[(base) + row * 88 + c]        = kr0;                       \
    *(uint4*)&smh[(base) + 5632 + row * 88 + c] = vr0; }                     \
  { int idx = t + 256; int row = idx >> 3, c = (idx & 7) * 8;                \
    *(uint4*)&smh[(base) + row * 88 + c]        = kr1;                       \
    *(uint4*)&smh[(base) + 5632 + row * 88 + c] = vr1; }

__global__ __launch_bounds__(256) void attn_f16_kernel() {
  extern __shared__ __align__(16) __half smh[];

  const int t    = threadIdx.x;
  const int lane = t & 31;
  const int warp = t >> 5;
  const int rw   = warp * 16;
  const int b    = blockIdx.z;
  const int h    = blockIdx.y;
  const int sQ   = blockIdx.x * 128;

  const int l8  = lane & 7;
  const int mhi = (lane >> 3) & 1;
  const int mvh = (lane >> 4) & 1;

  const size_t baseQK = (size_t)(b * Hn + h) * Sn * HDn;
  const size_t baseV  = (size_t)(b * Hn + h) * HDn * Sn;

  uint4 kr0, kr1, vr0, vr1;

  // Q tile into smem
#pragma unroll
  for (int i = 0; i < 4; i++) {
    int idx = t + i * 256;
    int row = idx >> 3, c = (idx & 7) * 8;
    *(uint4*)&smh[row * 88 + c] =
        *(const uint4*)&g_qh[baseQK + (size_t)(sQ + row) * HDn + c];
  }

  ATT_LOAD(0)
  ATT_STORE(AT_KV0)
  __syncthreads();

  // Hoist Q A-fragments via ldmatrix (4 x LDSM.x4 = all 16 frags)
  unsigned qa[4][4];
#pragma unroll
  for (int ks = 0; ks < 4; ks++) {
    const int rowQ = rw + mhi * 8 + l8;
    const int kQ   = ks * 16 + mvh * 8;
    LDSM4(qa[ks][0], qa[ks][1], qa[ks][2], qa[ks][3],
          SMEM_U32(&smh[rowQ * 88 + kQ]));
  }

  float m0 = -INFINITY, m1 = -INFINITY, l0 = 0.0f, l1 = 0.0f;
  float o[8][4];
#pragma unroll
  for (int nd = 0; nd < 8; nd++)
#pragma unroll
    for (int j = 0; j < 4; j++) o[nd][j] = 0.0f;

  for (int it = 0; it < Sn / 64; it++) {
    const int ksb = AT_KV0 + (it & 1) * AT_STG;
    const int vsb = ksb + 5632;
    if (it + 1 < Sn / 64) ATT_LOAD((it + 1) * 64)

    // S = Q K^T : K frags via LDSM (non-trans, [key][d] = [n][k])
    float sa[8][4];
#pragma unroll
    for (int nt = 0; nt < 8; nt++)
#pragma unroll
      for (int j = 0; j < 4; j++) sa[nt][j] = 0.0f;

#pragma unroll
    for (int ks = 0; ks < 4; ks++) {
#pragma unroll
      for (int ng = 0; ng < 4; ng++) {
        // m0=(nb,kb) m1=(nb,kb+8) m2=(nb+8,kb) m3=(nb+8,kb+8)
        const int nrow = ng * 16 + mvh * 8 + l8;
        const int kofs = ks * 16 + mhi * 8;
        unsigned b0, b1, b2, b3;
        LDSM4(b0, b1, b2, b3, SMEM_U32(&smh[ksb + nrow * 88 + kofs]));
        const int nt0 = ng * 2, nt1 = ng * 2 + 1;
        MMA_F16(sa[nt0][0], sa[nt0][1], sa[nt0][2], sa[nt0][3],
                qa[ks][0], qa[ks][1], qa[ks][2], qa[ks][3], b0, b1);
        MMA_F16(sa[nt1][0], sa[nt1][1], sa[nt1][2], sa[nt1][3],
                qa[ks][0], qa[ks][1], qa[ks][2], qa[ks][3], b2, b3);
      }
    }

    // Register softmax
    float mx0 = -INFINITY, mx1 = -INFINITY;
#pragma unroll
    for (int nt = 0; nt < 8; nt++) {
      mx0 = fmaxf(mx0, fmaxf(sa[nt][0], sa[nt][1]));
      mx1 = fmaxf(mx1, fmaxf(sa[nt][2], sa[nt][3]));
    }
    mx0 = fmaxf(mx0, __shfl_xor_sync(0xffffffffu, mx0, 1));
    mx0 = fmaxf(mx0, __shfl_xor_sync(0xffffffffu, mx0, 2));
    mx1 = fmaxf(mx1, __shfl_xor_sync(0xffffffffu, mx1, 1));
    mx1 = fmaxf(mx1, __shfl_xor_sync(0xffffffffu, mx1, 2));
    const float mn0 = fmaxf(m0, mx0);
    const float mn1 = fmaxf(m1, mx1);
    const float cr0 = __expf(m0 - mn0);
    const float cr1 = __expf(m1 - mn1);
    m0 = mn0; m1 = mn1;

    float sum0 = 0.0f, sum1 = 0.0f;
#pragma unroll
    for (int nt = 0; nt < 8; nt++) {
      sa[nt][0] = __expf(sa[nt][0] - mn0);
      sa[nt][1] = __expf(sa[nt][1] - mn0);
      sa[nt][2] = __expf(sa[nt][2] - mn1);
      sa[nt][3] = __expf(sa[nt][3] - mn1);
      sum0 += sa[nt][0] + sa[nt][1];
      sum1 += sa[nt][2] + sa[nt][3];
    }
    sum0 += __shfl_xor_sync(0xffffffffu, sum0, 1);
    sum0 += __shfl_xor_sync(0xffffffffu, sum0, 2);
    sum1 += __shfl_xor_sync(0xffffffffu, sum1, 1);
    sum1 += __shfl_xor_sync(0xffffffffu, sum1, 2);
    l0 = l0 * cr0 + sum0;
    l1 = l1 * cr1 + sum1;

#pragma unroll
    for (int nd = 0; nd < 8; nd++) {
      o[nd][0] *= cr0; o[nd][1] *= cr0;
      o[nd][2] *= cr1; o[nd][3] *= cr1;
    }

    // O += P @ V : V frags via LDSM (non-trans, [d][key] = [n][k])
#pragma unroll
    for (int kp = 0; kp < 4; kp++) {
      unsigned pa0, pa1, pa2, pa3;
      F22H(pa0, sa[2 * kp][0], sa[2 * kp][1]);
      F22H(pa1, sa[2 * kp][2], sa[2 * kp][3]);
      F22H(pa2, sa[2 * kp + 1][0], sa[2 * kp + 1][1]);
      F22H(pa3, sa[2 * kp + 1][2], sa[2 * kp + 1][3]);
#pragma unroll
      for (int ng = 0; ng < 4; ng++) {
        const int drow = ng * 16 + mvh * 8 + l8;
        const int kofs = kp * 16 + mhi * 8;
        unsigned b0, b1, b2, b3;
        LDSM4(b0, b1, b2, b3, SMEM_U32(&smh[vsb + drow * 88 + kofs]));
        const int nd0 = ng * 2, nd1 = ng * 2 + 1;
        MMA_F16(o[nd0][0], o[nd0][1], o[nd0][2], o[nd0][3],
                pa0, pa1, pa2, pa3, b0, b1);
        MMA_F16(o[nd1][0], o[nd1][1], o[nd1][2], o[nd1][3],
                pa0, pa1, pa2, pa3, b2, b3);
      }
    }

    if (it + 1 < Sn / 64) ATT_STORE(AT_KV0 + ((it + 1) & 1) * AT_STG)
    __syncthreads();
  }

  const int lq = lane >> 2;
  const int lt = lane & 3;
  const float i0 = 1.0f / l0;
  const float i1 = 1.0f / l1;
  const size_t row0 = (size_t)(b * Sn + sQ + rw + lq) * Dn + h * HDn;
  const size_t row1 = (size_t)(b * Sn + sQ + rw + lq + 8) * Dn + h * HDn;
#pragma unroll
  for (int nd = 0; nd < 8; nd++) {
    const int c = nd * 8 + lt * 2;
    unsigned u0, u1;
    F22H(u0, o[nd][0] * i0, o[nd][1] * i0);
    F22H(u1, o[nd][2] * i1, o[nd][3] * i1);
    *(unsigned*)&g_ctxh[row0 + c] = u0;
    *(unsigned*)&g_ctxh[row1 + c] = u1;
  }
}

// ---------------------------------------------------------------------------
// Residual + LayerNorm (fp32, unchanged)
// ---------------------------------------------------------------------------
__device__ __forceinline__ float block_sum(float v, float* red) {
#pragma unroll
  for (int o = 16; o; o >>= 1) v += __shfl_xor_sync(0xffffffffu, v, o);
  if ((threadIdx.x & 31) == 0) red[threadIdx.x >> 5] = v;
  __syncthreads();
  float tot = red[0] + red[1] + red[2] + red[3] +
              red[4] + red[5] + red[6] + red[7];
  __syncthreads();
  return tot;
}

__global__ __launch_bounds__(256) void ln_kernel(
    const float* __restrict__ x, const float* __restrict__ gamma,
    const float* __restrict__ beta, float* __restrict__ out) {
  __shared__ float red[8];
  const int row = blockIdx.x;
  const int c   = threadIdx.x * 4;

  float4 y  = *(const float4*)&g_proj[(size_t)row * Dn + c];
  float4 xv = *(const float4*)&x[(size_t)row * Dn + c];
  y.x += xv.x; y.y += xv.y; y.z += xv.z; y.w += xv.w;

  float tot = block_sum(y.x + y.y + y.z + y.w, red);
  const float mu = tot * (1.0f / Dn);

  float dx = y.x - mu, dy = y.y - mu, dz = y.z - mu, dw = y.w - mu;
  float sq = block_sum(dx * dx + dy * dy + dz * dz + dw * dw, red);
  const float var = sq * (1.0f / Dn);
  const float r = rsqrtf(var + 1e-5f);

  float4 g  = *(const float4*)&gamma[c];
  float4 bt = *(const float4*)&beta[c];
  float4 o;
  o.x = dx * r * g.x + bt.x;
  o.y = dy * r * g.y + bt.y;
  o.z = dz * r * g.z + bt.z;
  o.w = dw * r * g.w + bt.w;
  *(float4*)&out[(size_t)row * Dn + c] = o;
}

// ---------------------------------------------------------------------------
// Launch — only harness pointers cross the host/device boundary.
// ---------------------------------------------------------------------------
extern "C" void kernel_launch(void* const* d_in, const int* in_sizes, int n_in,
                              void* d_out, int out_size) {
  (void)in_sizes; (void)n_in; (void)out_size;
  const float* x     = (const float*)d_in[0];
  const float* W_qkv = (const float*)d_in[1];
  const float* b_qkv = (const float*)d_in[2];
  const float* W_out = (const float*)d_in[3];
  const float* b_out = (const float*)d_in[4];
  const float* gamma = (const float*)d_in[5];
  const float* beta  = (const float*)d_in[6];
  float* out = (float*)d_out;

  cudaFuncSetAttribute(attn_f16_kernel,
                       cudaFuncAttributeMaxDynamicSharedMemorySize,
                       ATTN_SMEM_BYTES);

  cvt_x_kernel<<<(Bn * Sn * Dn) / 1024, 256>>>(x);
  cvt_w_kernel<1><<<(Dn * N3) / 1024, 256>>>(W_qkv);
  cvt_w_kernel<0><<<(Dn * Dn) / 1024, 256>>>(W_out);

  gemm_f16_kernel<N3, 1><<<dim3(N3 / 128, (Bn * Sn) / 128), 256>>>(b_qkv);
  attn_f16_kernel<<<dim3(Sn / 128, Hn, Bn), 256, ATTN_SMEM_BYTES>>>();
  gemm_f16_kernel<Dn, 0><<<dim3(Dn / 128, (Bn * Sn) / 128), 256>>>(b_out);
  ln_kernel<<<Bn * Sn, 256>>>(x, gamma, beta, out);
}